// round 13
// baseline (speedup 1.0000x reference)
#include <cuda_runtime.h>
#include <cuda_bf16.h>
#include <math.h>
#include <stdint.h>

#define B_   4
#define N_   256
#define Kd   128
#define S_   256
#define BKt  512
#define BE   65536
#define SCALE 0.0625f

__device__ __align__(256) float          g_pe [S_ * N_];      // [s][n]
__device__ __align__(256) float          g_peT[N_ * S_];      // [n][s]
__device__ __align__(256) float          g_mu1[BKt * S_];
__device__ __align__(256) float          g_rs1[BKt * S_];
__device__ __align__(256) float          g_wkq[N_];           // Wk^T qb
__device__ __align__(256) float          g_vcol[BKt * S_];    // h_k . (Wk^T qb)
__device__ __align__(256) __nv_bfloat16  g_hb[BKt * BE];      // bf16 [bk][s][n]
__device__ __align__(256) __nv_bfloat16  g_Tb[BKt * BE];      // T = h.M  [bk][q][m]
__device__ __align__(256) __nv_bfloat16  g_Vt[BKt * BE];      // [bk][j][s]
__device__ __align__(256) __nv_bfloat16  g_wv[N_ * N_];       // Wv bf16 [j][n]
__device__ __align__(256) __nv_bfloat16  g_Mb[N_ * N_];       // Mb[m][n] = M[n][m]

// ---------------- helpers ----------------
__device__ __forceinline__ uint32_t smem_u32(const void* p) {
    uint32_t a;
    asm("{ .reg .u64 t; cvta.to.shared.u64 t, %1; cvt.u32.u64 %0, t; }" : "=r"(a) : "l"(p));
    return a;
}
__device__ __forceinline__ void cpasync16(uint32_t dst, const void* src) {
    asm volatile("cp.async.cg.shared.global [%0], [%1], 16;" :: "r"(dst), "l"(src));
}
#define CP_COMMIT() asm volatile("cp.async.commit_group;" ::: "memory")
#define CP_WAIT0()  asm volatile("cp.async.wait_group 0;" ::: "memory")
#define CP_WAIT1()  asm volatile("cp.async.wait_group 1;" ::: "memory")

__device__ __forceinline__ void ldmat4(uint32_t& r0, uint32_t& r1, uint32_t& r2, uint32_t& r3, uint32_t addr) {
    asm volatile("ldmatrix.sync.aligned.m8n8.x4.shared.b16 {%0,%1,%2,%3}, [%4];"
                 : "=r"(r0), "=r"(r1), "=r"(r2), "=r"(r3) : "r"(addr));
}
__device__ __forceinline__ void mma16816(float* d, const uint32_t* a, const uint32_t* b) {
    asm volatile("mma.sync.aligned.m16n8k16.row.col.f32.bf16.bf16.f32 "
                 "{%0,%1,%2,%3},{%4,%5,%6,%7},{%8,%9},{%0,%1,%2,%3};"
                 : "+f"(d[0]), "+f"(d[1]), "+f"(d[2]), "+f"(d[3])
                 : "r"(a[0]), "r"(a[1]), "r"(a[2]), "r"(a[3]), "r"(b[0]), "r"(b[1]));
}
// gmem [rows x 64] bf16 (row stride 256) -> smem SW128 [rows][128B]
__device__ __forceinline__ void tile_cp(uint32_t dst, const __nv_bfloat16* __restrict__ src,
                                        int rows, int tid, int nthr) {
    int total = rows * 8;
    for (int u = tid; u < total; u += nthr) {
        int row = u >> 3, seg = u & 7;
        cpasync16(dst + row * 128 + (((uint32_t)(seg ^ (row & 7))) << 4), src + row * 256 + seg * 8);
    }
}
__device__ __forceinline__ uint32_t a_addr(uint32_t base, int m0, int ksg, int lane) {
    int row = m0 + (lane & 15);
    int seg = ksg + (lane >> 4);
    return base + row * 128 + (((uint32_t)(seg ^ (row & 7))) << 4);
}
__device__ __forceinline__ uint32_t b_addr(uint32_t base, int n0, int ksg, int lane) {
    int row = n0 + ((lane >> 4) << 3) + (lane & 7);
    int seg = ksg + ((lane >> 3) & 1);
    return base + row * 128 + (((uint32_t)(seg ^ (row & 7))) << 4);
}

// ---------------------------------------------------------------------------
__global__ void pe_kernel() {
    int s = blockIdx.x, n = threadIdx.x;
    float freq = __expf(-(float)(n & ~1) * (9.210340371976184f / 256.0f));
    float a = (float)s * freq;
    float v = (n & 1) ? cosf(a) : sinf(a);
    g_pe [s * N_ + n] = v;
    g_peT[n * S_ + s] = v;
}

__global__ void wconv_kernel(const float* __restrict__ vw) {
    int i = blockIdx.x * 256 + threadIdx.x;
    g_wv[i] = __float2bfloat16(vw[i]);
}

// M[n][m] = sum_i qw[i][n]*kw[i][m]; store Mb[m][n]=M[n][m]. wkq[m]=sum_i qb[i]kw[i][m].
__global__ void __launch_bounds__(256) mk_kernel(const float* __restrict__ qw,
                                                 const float* __restrict__ kw,
                                                 const float* __restrict__ qb) {
    __shared__ float kcol[256];
    __shared__ float part[256];
    int m = blockIdx.x, n = threadIdx.x;
    kcol[n] = kw[n * 256 + m];
    part[n] = qb[n] * kcol[n];
    __syncthreads();
    if (n == 0) {
        float s = 0.f;
        for (int i = 0; i < 256; i++) s += part[i];
        g_wkq[m] = s;
    }
    float s = 0.f;
#pragma unroll 4
    for (int i = 0; i < 256; i++) s += kcol[i] * qw[i * 256 + n];
    g_Mb[m * 256 + n] = __float2bfloat16(s);
}

// LN1 stats + bf16 h + fused vcol. Grid (bk, 2). Thread = (s-quad, n-range-32).
__global__ void __launch_bounds__(256) ln1_kernel(const float* __restrict__ x,
                                                  const float* __restrict__ w1,
                                                  const float* __restrict__ b1) {
    __shared__ float ps1[8 * 128], ps2[8 * 128];
    __shared__ float muS[128], rsS[128];
    __shared__ float w1s[256], b1s[256], wkqs[256];
    __shared__ float vp[8 * 128];
    int bk = blockIdx.x, half = blockIdx.y;
    int b = bk >> 7, k = bk & 127;
    int tid = threadIdx.x;
    int s_base = half * 128;
    const float* xb = x + ((size_t)b * N_ * Kd + k) * S_ + s_base;
    int sq = tid & 31;
    int nr = tid >> 5;
    int s4 = sq * 4;

    // ---- stats pass ----
    {
        float a1 = 0.f, a2 = 0.f, b1a = 0.f, b2a = 0.f, c1 = 0.f, c2 = 0.f, d1 = 0.f, d2 = 0.f;
        const float* xp = xb + (size_t)(nr * 32) * (Kd * S_) + s4;
#pragma unroll 8
        for (int i = 0; i < 32; i++) {
            float4 v = *(const float4*)(xp + (size_t)i * (Kd * S_));
            a1 += v.x; a2 += v.x * v.x;
            b1a += v.y; b2a += v.y * v.y;
            c1 += v.z; c2 += v.z * v.z;
            d1 += v.w; d2 += v.w * v.w;
        }
        ps1[nr * 128 + s4 + 0] = a1;  ps2[nr * 128 + s4 + 0] = a2;
        ps1[nr * 128 + s4 + 1] = b1a; ps2[nr * 128 + s4 + 1] = b2a;
        ps1[nr * 128 + s4 + 2] = c1;  ps2[nr * 128 + s4 + 2] = c2;
        ps1[nr * 128 + s4 + 3] = d1;  ps2[nr * 128 + s4 + 3] = d2;
    }
    w1s[tid] = w1[tid];
    b1s[tid] = b1[tid];
    wkqs[tid] = g_wkq[tid];
    __syncthreads();
    if (tid < 128) {
        float s1 = 0.f, s2 = 0.f;
#pragma unroll
        for (int g = 0; g < 8; g++) { s1 += ps1[g * 128 + tid]; s2 += ps2[g * 128 + tid]; }
        float mu = s1 * (1.f / N_);
        float var = s2 * (1.f / N_) - mu * mu;
        float rs = rsqrtf(var + 1e-5f);
        muS[tid] = mu;
        rsS[tid] = rs;
        g_mu1[bk * S_ + s_base + tid] = mu;
        g_rs1[bk * S_ + s_base + tid] = rs;
    }
    __syncthreads();

    // ---- write pass ----
    __nv_bfloat16* hb = g_hb + (size_t)bk * BE;
    float accv[4] = {0.f, 0.f, 0.f, 0.f};
    float mus[4], rss[4];
#pragma unroll
    for (int si = 0; si < 4; si++) { mus[si] = muS[s4 + si]; rss[si] = rsS[s4 + si]; }

#pragma unroll
    for (int oct = 0; oct < 4; oct++) {
        int n0 = nr * 32 + oct * 8;
        float4 xv[8];
#pragma unroll
        for (int i = 0; i < 8; i++)
            xv[i] = *(const float4*)(xb + (size_t)(n0 + i) * (Kd * S_) + s4);
        float w1v[8], b1v[8], wkv[8];
#pragma unroll
        for (int i = 0; i < 8; i++) { w1v[i] = w1s[n0 + i]; b1v[i] = b1s[n0 + i]; wkv[i] = wkqs[n0 + i]; }
#pragma unroll
        for (int si = 0; si < 4; si++) {
            int s_glob = s_base + s4 + si;
            const float4* pep = (const float4*)(g_pe + (size_t)s_glob * N_ + n0);
            float4 pe0 = pep[0], pe1 = pep[1];
            float pev[8] = {pe0.x, pe0.y, pe0.z, pe0.w, pe1.x, pe1.y, pe1.z, pe1.w};
            uint32_t pk[4];
#pragma unroll
            for (int p = 0; p < 4; p++) {
                float x0 = ((const float*)&xv[2 * p])[si];
                float x1 = ((const float*)&xv[2 * p + 1])[si];
                float hv0 = (x0 - mus[si]) * rss[si] * w1v[2 * p]     + b1v[2 * p]     + pev[2 * p];
                float hv1 = (x1 - mus[si]) * rss[si] * w1v[2 * p + 1] + b1v[2 * p + 1] + pev[2 * p + 1];
                accv[si] += hv0 * wkv[2 * p] + hv1 * wkv[2 * p + 1];
                __nv_bfloat162 t = __floats2bfloat162_rn(hv0, hv1);
                pk[p] = *(uint32_t*)&t;
            }
            *(uint4*)(hb + (size_t)s_glob * N_ + n0) = make_uint4(pk[0], pk[1], pk[2], pk[3]);
        }
    }
#pragma unroll
    for (int si = 0; si < 4; si++) vp[nr * 128 + s4 + si] = accv[si];
    __syncthreads();
    if (tid < 128) {
        float s = 0.f;
#pragma unroll
        for (int g = 0; g < 8; g++) s += vp[g * 128 + tid];
        g_vcol[bk * 256 + s_base + tid] = s;
    }
}

// ---------------- qkv_mma: which=0 -> T=h.M ; which=1 -> Vt=Wv.h^T ---------
#define Q_A0   0
#define Q_A1   16384
#define Q_B0   32768
#define Q_B1   49152
#define Q_BIAS 65536
#define Q_SMEM 66560

__global__ void __launch_bounds__(256, 2)
qkv_mma(const float* __restrict__ vb_) {
    extern __shared__ char smem_dyn[];
    uint32_t sb = smem_u32(smem_dyn);
    int tid = threadIdx.x, lane = tid & 31, wid = tid >> 5;
    int wm = wid >> 2, wn = wid & 3;
    int m_base = wm * 64, n_base = wn * 32;

    int mt = blockIdx.x >> 1, nt = blockIdx.x & 1;
    int which = blockIdx.y, bk = blockIdx.z;

    const __nv_bfloat16* hb = g_hb + (size_t)bk * BE;
    const __nv_bfloat16 *Ag, *Bg;
    __nv_bfloat16* outp;
    if (which == 0) { Ag = hb + mt * 128 * 256;     Bg = g_Mb + nt * 128 * 256; outp = g_Tb + (size_t)bk * BE; }
    else            { Ag = g_wv + mt * 128 * 256;   Bg = hb + nt * 128 * 256;   outp = g_Vt + (size_t)bk * BE; }

    float* biass = (float*)(smem_dyn + Q_BIAS);
    if (tid < 256) biass[tid] = vb_[tid];

    float acc[4][4][4] = {};

    tile_cp(sb + Q_A0, Ag, 128, tid, 256);
    tile_cp(sb + Q_B0, Bg, 128, tid, 256);
    CP_COMMIT();

    for (int c = 0; c < 4; c++) {
        int cur = c & 1;
        if (c + 1 < 4) {
            tile_cp(sb + (cur ? Q_A0 : Q_A1), Ag + (c + 1) * 64, 128, tid, 256);
            tile_cp(sb + (cur ? Q_B0 : Q_B1), Bg + (c + 1) * 64, 128, tid, 256);
            CP_COMMIT();
            CP_WAIT1();
        } else {
            CP_WAIT0();
        }
        __syncthreads();
        uint32_t aB = sb + (cur ? Q_A1 : Q_A0);
        uint32_t bB = sb + (cur ? Q_B1 : Q_B0);
#pragma unroll
        for (int kk = 0; kk < 4; kk++) {
            int ksg = kk * 2;
            uint32_t a[4][4];
#pragma unroll
            for (int mi = 0; mi < 4; mi++)
                ldmat4(a[mi][0], a[mi][1], a[mi][2], a[mi][3], a_addr(aB, m_base + mi * 16, ksg, lane));
            uint32_t bfr[4][2];
#pragma unroll
            for (int nj = 0; nj < 2; nj++) {
                uint32_t r0, r1, r2, r3;
                ldmat4(r0, r1, r2, r3, b_addr(bB, n_base + nj * 16, ksg, lane));
                bfr[nj * 2][0] = r0;     bfr[nj * 2][1] = r1;
                bfr[nj * 2 + 1][0] = r2; bfr[nj * 2 + 1][1] = r3;
            }
#pragma unroll
            for (int mi = 0; mi < 4; mi++)
#pragma unroll
                for (int ni = 0; ni < 4; ni++)
                    mma16816(acc[mi][ni], a[mi], bfr[ni]);
        }
        __syncthreads();
    }

#pragma unroll
    for (int mi = 0; mi < 4; mi++) {
#pragma unroll
        for (int h = 0; h < 2; h++) {
            int rloc = m_base + mi * 16 + h * 8 + (lane >> 2);
            int grow = mt * 128 + rloc;
            float rb = (which == 1) ? biass[grow] : 0.f;
#pragma unroll
            for (int ni = 0; ni < 4; ni++) {
                int cloc = n_base + ni * 8 + (lane & 3) * 2;
                int gcol = nt * 128 + cloc;
                float v0 = acc[mi][ni][h * 2 + 0] + rb;
                float v1 = acc[mi][ni][h * 2 + 1] + rb;
                __nv_bfloat162 t = __floats2bfloat162_rn(v0, v1);
                *(uint32_t*)(outp + grow * 256 + gcol) = *(uint32_t*)&t;
            }
        }
    }
}

// ---------------- attn_mma: per (bk, 64-q tile), warps 32x64 ----------------
#define A_QS   0
#define A_BS   32768
#define A_PS   65536
#define A_RED  98304
#define A_FROW 99328
#define A_MU1  99584
#define A_RS1  99840
#define A_MU2  100096
#define A_RS2  100352
#define A_W1   100608
#define A_B1   101632
#define A_W2   102656
#define A_B2   103680
#define A_VC   104704
#define A_SMEM 105728

__global__ void __launch_bounds__(256, 2)
attn_mma(const float* __restrict__ x, float* __restrict__ out,
         const float* __restrict__ w2, const float* __restrict__ b2,
         const float* __restrict__ w1, const float* __restrict__ b1) {
    extern __shared__ char smem_dyn[];
    uint32_t sb = smem_u32(smem_dyn);
    int tid = threadIdx.x, lane = tid & 31, wid = tid >> 5;
    int wm = wid >> 2, wn = wid & 3;
    int q0 = blockIdx.x * 64;
    int bk = blockIdx.y;

    float* sRed  = (float*)(smem_dyn + A_RED);
    float* frowS = (float*)(smem_dyn + A_FROW);
    float* mu1s  = (float*)(smem_dyn + A_MU1);
    float* rs1s  = (float*)(smem_dyn + A_RS1);
    float* mu2s  = (float*)(smem_dyn + A_MU2);
    float* rs2s  = (float*)(smem_dyn + A_RS2);
    float* w1s   = (float*)(smem_dyn + A_W1);
    float* b1s   = (float*)(smem_dyn + A_B1);
    float* w2s   = (float*)(smem_dyn + A_W2);
    float* b2s   = (float*)(smem_dyn + A_B2);
    float* vcS   = (float*)(smem_dyn + A_VC);
    if (tid < 256) {
        w1s[tid] = w1[tid]; b1s[tid] = b1[tid];
        w2s[tid] = w2[tid]; b2s[tid] = b2[tid];
        vcS[tid] = g_vcol[bk * 256 + tid];
    }
    if (tid < 64)  { mu1s[tid] = g_mu1[bk * S_ + q0 + tid]; rs1s[tid] = g_rs1[bk * S_ + q0 + tid]; }

    const __nv_bfloat16* Qg = g_Tb + (size_t)bk * BE + q0 * 256;
    const __nv_bfloat16* Kg = g_hb + (size_t)bk * BE;
    const __nv_bfloat16* Vg = g_Vt + (size_t)bk * BE;

    float acc[2][8][4] = {};

    // ---- phase 1: logits = T . h^T ----
    for (int jc = 0; jc < 4; jc++)
        tile_cp(sb + A_QS + jc * 8192, Qg + jc * 64, 64, tid, 256);
    tile_cp(sb + A_BS, Kg, 256, tid, 256);
    CP_COMMIT();
    for (int jc = 0; jc < 4; jc++) {
        if (jc < 3) {
            tile_cp(sb + ((jc & 1) ? A_BS : A_PS), Kg + (jc + 1) * 64, 256, tid, 256);
            CP_COMMIT(); CP_WAIT1();
        } else CP_WAIT0();
        __syncthreads();
        uint32_t aB = sb + A_QS + jc * 8192;
        uint32_t bB = sb + ((jc & 1) ? A_PS : A_BS);
#pragma unroll
        for (int kk = 0; kk < 4; kk++) {
            int ksg = kk * 2;
            uint32_t a[2][4];
#pragma unroll
            for (int mi = 0; mi < 2; mi++)
                ldmat4(a[mi][0], a[mi][1], a[mi][2], a[mi][3], a_addr(aB, wm * 32 + mi * 16, ksg, lane));
#pragma unroll
            for (int nj = 0; nj < 4; nj++) {
                uint32_t r0, r1, r2, r3;
                ldmat4(r0, r1, r2, r3, b_addr(bB, wn * 64 + nj * 16, ksg, lane));
                uint32_t b0[2] = {r0, r1}, b1v[2] = {r2, r3};
#pragma unroll
                for (int mi = 0; mi < 2; mi++) {
                    mma16816(acc[mi][nj * 2],     a[mi], b0);
                    mma16816(acc[mi][nj * 2 + 1], a[mi], b1v);
                }
            }
        }
        __syncthreads();
    }

    // prefetch V chunk0 -> BS and chunk1 -> QS (Q is dead); overlaps softmax
    tile_cp(sb + A_BS, Vg, 256, tid, 256);
    CP_COMMIT();
    tile_cp(sb + A_QS, Vg + 64, 256, tid, 256);
    CP_COMMIT();

    // ---- softmax (no max subtraction: logits are O(10), exp safe in fp32);
    //      vcol folded into exp argument ----
#pragma unroll
    for (int mi = 0; mi < 2; mi++)
#pragma unroll
        for (int h = 0; h < 2; h++) {
            int r = wm * 32 + mi * 16 + h * 8 + (lane >> 2);
            float ps = 0.f;
#pragma unroll
            for (int ni = 0; ni < 8; ni++) {
                int k0 = wn * 64 + ni * 8 + (lane & 3) * 2;
                float e0 = __expf(acc[mi][ni][h * 2 + 0] + vcS[k0]);
                float e1 = __expf(acc[mi][ni][h * 2 + 1] + vcS[k0 + 1]);
                ps += e0 + e1;
                __nv_bfloat162 t = __floats2bfloat162_rn(e0, e1);
                int cl = k0 & 63;
                int cb = cl * 2;
                uint32_t addr = sb + A_PS + wn * 8192 + r * 128
                              + ((((uint32_t)cb >> 4) ^ (uint32_t)(r & 7)) << 4) + (cb & 15);
                asm volatile("st.shared.b32 [%0], %1;" :: "r"(addr), "r"(*(uint32_t*)&t));
            }
            ps += __shfl_xor_sync(0xffffffffu, ps, 1);
            ps += __shfl_xor_sync(0xffffffffu, ps, 2);
            if ((lane & 3) == 0) sRed[wn * 64 + r] = ps;
        }
    __syncthreads();
    if (tid < 64)
        frowS[tid] = SCALE / (sRed[tid] + sRed[64 + tid] + sRed[128 + tid] + sRed[192 + tid]);
#pragma unroll
    for (int mi = 0; mi < 2; mi++)
#pragma unroll
        for (int ni = 0; ni < 8; ni++)
#pragma unroll
            for (int j = 0; j < 4; j++) acc[mi][ni][j] = 0.f;
    __syncthreads();

    // ---- phase 2: O = expP . Vt^T (2-deep prefetched: c0 in BS, c1 in QS) ----
    for (int sc = 0; sc < 4; sc++) {
        if (sc < 3) CP_WAIT1(); else CP_WAIT0();
        __syncthreads();
        uint32_t aB = sb + A_PS + sc * 8192;
        uint32_t bB = sb + ((sc & 1) ? A_QS : A_BS);
#pragma unroll
        for (int kk = 0; kk < 4; kk++) {
            int ksg = kk * 2;
            uint32_t a[2][4];
#pragma unroll
            for (int mi = 0; mi < 2; mi++)
                ldmat4(a[mi][0], a[mi][1], a[mi][2], a[mi][3], a_addr(aB, wm * 32 + mi * 16, ksg, lane));
#pragma unroll
            for (int nj = 0; nj < 4; nj++) {
                uint32_t r0, r1, r2, r3;
                ldmat4(r0, r1, r2, r3, b_addr(bB, wn * 64 + nj * 16, ksg, lane));
                uint32_t b0[2] = {r0, r1}, b1v[2] = {r2, r3};
#pragma unroll
                for (int mi = 0; mi < 2; mi++) {
                    mma16816(acc[mi][nj * 2],     a[mi], b0);
                    mma16816(acc[mi][nj * 2 + 1], a[mi], b1v);
                }
            }
        }
        __syncthreads();
        if (sc + 2 < 4) {
            tile_cp(sb + ((sc & 1) ? A_QS : A_BS), Vg + (sc + 2) * 64, 256, tid, 256);
            CP_COMMIT();
        }
    }

    // ---- epilogue ----
    float* Os = (float*)smem_dyn;   // [64][257]
#pragma unroll
    for (int mi = 0; mi < 2; mi++)
#pragma unroll
        for (int h = 0; h < 2; h++) {
            int r = wm * 32 + mi * 16 + h * 8 + (lane >> 2);
            float fr = frowS[r];
#pragma unroll
            for (int ni = 0; ni < 8; ni++) {
                int d = wn * 64 + ni * 8 + (lane & 3) * 2;
                Os[r * 257 + d]     = acc[mi][ni][h * 2 + 0] * fr;
                Os[r * 257 + d + 1] = acc[mi][ni][h * 2 + 1] * fr;
            }
        }
    __syncthreads();

    int b = bk >> 7, kk2 = bk & 127;
    const float* xb = x   + (size_t)b * (N_ * Kd * S_) + kk2 * S_ + q0;
    float*       ob = out + (size_t)b * (N_ * Kd * S_) + kk2 * S_ + q0;

#pragma unroll 4
    for (int it = 0; it < 64; it++) {
        int idx = it * 256 + tid;
        int qi = idx & 63, d = idx >> 6;
        float xv = xb[d * (Kd * S_) + qi];
        float hv = (xv - mu1s[qi]) * rs1s[qi] * w1s[d] + b1s[d] + g_peT[d * S_ + q0 + qi];
        Os[qi * 257 + d] += hv;
    }
    __syncthreads();

    {
        int r = tid >> 2, sub = tid & 3;
        float s1 = 0.f, s2 = 0.f;
#pragma unroll 8
        for (int j = 0; j < 64; j++) {
            float v = Os[r * 257 + sub * 64 + j];
            s1 += v; s2 += v * v;
        }
        s1 += __shfl_xor_sync(0xffffffffu, s1, 1); s2 += __shfl_xor_sync(0xffffffffu, s2, 1);
        s1 += __shfl_xor_sync(0xffffffffu, s1, 2); s2 += __shfl_xor_sync(0xffffffffu, s2, 2);
        if (sub == 0) {
            float mu = s1 * (1.f / N_);
            float var = s2 * (1.f / N_) - mu * mu;
            mu2s[r] = mu;
            rs2s[r] = rsqrtf(var + 1e-5f);
        }
    }
    __syncthreads();

#pragma unroll 4
    for (int it = 0; it < 64; it++) {
        int idx = it * 256 + tid;
        int qi = idx & 63, d = idx >> 6;
        float v = Os[qi * 257 + d];
        float o = (v - mu2s[qi]) * rs2s[qi] * w2s[d] + b2s[d] + xb[d * (Kd * S_) + qi];
        ob[d * (Kd * S_) + qi] = o;
    }
}

extern "C" void kernel_launch(void* const* d_in, const int* in_sizes, int n_in,
                              void* d_out, int out_size) {
    const float* x    = (const float*)d_in[0];
    const float* ln1w = (const float*)d_in[1];
    const float* ln1b = (const float*)d_in[2];
    const float* qw   = (const float*)d_in[3];
    const float* qb   = (const float*)d_in[4];
    const float* kw   = (const float*)d_in[5];
    const float* kb   = (const float*)d_in[6];
    const float* vw   = (const float*)d_in[7];
    const float* vb   = (const float*)d_in[8];
    const float* w2   = (const float*)d_in[9];
    const float* b2   = (const float*)d_in[10];
    float* out = (float*)d_out;

    cudaFuncSetAttribute(qkv_mma,  cudaFuncAttributeMaxDynamicSharedMemorySize, Q_SMEM);
    cudaFuncSetAttribute(attn_mma, cudaFuncAttributeMaxDynamicSharedMemorySize, A_SMEM);

    pe_kernel<<<S_, N_>>>();
    wconv_kernel<<<256, 256>>>(vw);
    mk_kernel<<<256, 256>>>(qw, kw, qb);
    ln1_kernel<<<dim3(BKt, 2), 256>>>(x, ln1w, ln1b);
    qkv_mma<<<dim3(4, 2, BKt), 256, Q_SMEM>>>(vb);
    attn_mma<<<dim3(4, BKt), 256, A_SMEM>>>(x, out, w2, b2, ln1w, ln1b);
}

// round 14
// speedup vs baseline: 1.0189x; 1.0189x over previous
#include <cuda_runtime.h>
#include <cuda_bf16.h>
#include <math.h>
#include <stdint.h>

#define B_   4
#define N_   256
#define Kd   128
#define S_   256
#define BKt  512
#define BE   65536
#define SCALE 0.0625f

__device__ __align__(256) float          g_pe [S_ * N_];      // [s][n]
__device__ __align__(256) float          g_peT[N_ * S_];      // [n][s]
__device__ __align__(256) float          g_mu1[BKt * S_];
__device__ __align__(256) float          g_rs1[BKt * S_];
__device__ __align__(256) float          g_wkq[N_];           // Wk^T qb
__device__ __align__(256) float          g_vcol[BKt * S_];    // h_k . (Wk^T qb)
__device__ __align__(256) __nv_bfloat16  g_hb[BKt * BE];      // bf16 [bk][s][n]
__device__ __align__(256) __nv_bfloat16  g_Tb[BKt * BE];      // T = h.M  [bk][q][m]
__device__ __align__(256) __nv_bfloat16  g_Vt[BKt * BE];      // [bk][j][s]
__device__ __align__(256) __nv_bfloat16  g_wv[N_ * N_];       // Wv bf16 [j][n]
__device__ __align__(256) __nv_bfloat16  g_Mb[N_ * N_];       // Mb[m][n] = M[n][m]

// ---------------- helpers ----------------
__device__ __forceinline__ uint32_t smem_u32(const void* p) {
    uint32_t a;
    asm("{ .reg .u64 t; cvta.to.shared.u64 t, %1; cvt.u32.u64 %0, t; }" : "=r"(a) : "l"(p));
    return a;
}
__device__ __forceinline__ void cpasync16(uint32_t dst, const void* src) {
    asm volatile("cp.async.cg.shared.global [%0], [%1], 16;" :: "r"(dst), "l"(src));
}
#define CP_COMMIT() asm volatile("cp.async.commit_group;" ::: "memory")
#define CP_WAIT0()  asm volatile("cp.async.wait_group 0;" ::: "memory")
#define CP_WAIT1()  asm volatile("cp.async.wait_group 1;" ::: "memory")

__device__ __forceinline__ void ldmat4(uint32_t& r0, uint32_t& r1, uint32_t& r2, uint32_t& r3, uint32_t addr) {
    asm volatile("ldmatrix.sync.aligned.m8n8.x4.shared.b16 {%0,%1,%2,%3}, [%4];"
                 : "=r"(r0), "=r"(r1), "=r"(r2), "=r"(r3) : "r"(addr));
}
__device__ __forceinline__ void mma16816(float* d, const uint32_t* a, const uint32_t* b) {
    asm volatile("mma.sync.aligned.m16n8k16.row.col.f32.bf16.bf16.f32 "
                 "{%0,%1,%2,%3},{%4,%5,%6,%7},{%8,%9},{%0,%1,%2,%3};"
                 : "+f"(d[0]), "+f"(d[1]), "+f"(d[2]), "+f"(d[3])
                 : "r"(a[0]), "r"(a[1]), "r"(a[2]), "r"(a[3]), "r"(b[0]), "r"(b[1]));
}
// gmem [rows x 64] bf16 (row stride 256) -> smem SW128 [rows][128B]
__device__ __forceinline__ void tile_cp(uint32_t dst, const __nv_bfloat16* __restrict__ src,
                                        int rows, int tid, int nthr) {
    int total = rows * 8;
    for (int u = tid; u < total; u += nthr) {
        int row = u >> 3, seg = u & 7;
        cpasync16(dst + row * 128 + (((uint32_t)(seg ^ (row & 7))) << 4), src + row * 256 + seg * 8);
    }
}
__device__ __forceinline__ uint32_t a_addr(uint32_t base, int m0, int ksg, int lane) {
    int row = m0 + (lane & 15);
    int seg = ksg + (lane >> 4);
    return base + row * 128 + (((uint32_t)(seg ^ (row & 7))) << 4);
}
__device__ __forceinline__ uint32_t b_addr(uint32_t base, int n0, int ksg, int lane) {
    int row = n0 + ((lane >> 4) << 3) + (lane & 7);
    int seg = ksg + ((lane >> 3) & 1);
    return base + row * 128 + (((uint32_t)(seg ^ (row & 7))) << 4);
}

// ---------------------------------------------------------------------------
// setup: pe (block = s row), wv->bf16 (row), M column + wkq (block = m)
__global__ void __launch_bounds__(256) setup_kernel(const float* __restrict__ qw,
                                                    const float* __restrict__ kw,
                                                    const float* __restrict__ qb,
                                                    const float* __restrict__ vw) {
    __shared__ float kcol[256];
    __shared__ float part[256];
    int m = blockIdx.x, n = threadIdx.x;

    // pe row s = m
    float freq = __expf(-(float)(n & ~1) * (9.210340371976184f / 256.0f));
    float a = (float)m * freq;
    float v = (n & 1) ? cosf(a) : sinf(a);
    g_pe [m * N_ + n] = v;
    g_peT[n * S_ + m] = v;

    // wv -> bf16 (row m)
    g_wv[m * 256 + n] = __float2bfloat16(vw[m * 256 + n]);

    // mk: column m of M, plus wkq[m]
    kcol[n] = kw[n * 256 + m];
    part[n] = qb[n] * kcol[n];
    __syncthreads();
    if (n == 0) {
        float s = 0.f;
        for (int i = 0; i < 256; i++) s += part[i];
        g_wkq[m] = s;
    }
    float s = 0.f;
#pragma unroll 4
    for (int i = 0; i < 256; i++) s += kcol[i] * qw[i * 256 + n];
    g_Mb[m * 256 + n] = __float2bfloat16(s);
}

// LN1 stats + bf16 h + fused vcol. Grid (bk, 2). Thread = (s-quad, n-range-32).
__global__ void __launch_bounds__(256) ln1_kernel(const float* __restrict__ x,
                                                  const float* __restrict__ w1,
                                                  const float* __restrict__ b1) {
    __shared__ float ps1[8 * 128], ps2[8 * 128];
    __shared__ float muS[128], rsS[128];
    __shared__ float w1s[256], b1s[256], wkqs[256];
    __shared__ float vp[8 * 128];
    int bk = blockIdx.x, half = blockIdx.y;
    int b = bk >> 7, k = bk & 127;
    int tid = threadIdx.x;
    int s_base = half * 128;
    const float* xb = x + ((size_t)b * N_ * Kd + k) * S_ + s_base;
    int sq = tid & 31;
    int nr = tid >> 5;
    int s4 = sq * 4;

    // ---- stats pass ----
    {
        float a1 = 0.f, a2 = 0.f, b1a = 0.f, b2a = 0.f, c1 = 0.f, c2 = 0.f, d1 = 0.f, d2 = 0.f;
        const float* xp = xb + (size_t)(nr * 32) * (Kd * S_) + s4;
#pragma unroll 8
        for (int i = 0; i < 32; i++) {
            float4 v = *(const float4*)(xp + (size_t)i * (Kd * S_));
            a1 += v.x; a2 += v.x * v.x;
            b1a += v.y; b2a += v.y * v.y;
            c1 += v.z; c2 += v.z * v.z;
            d1 += v.w; d2 += v.w * v.w;
        }
        ps1[nr * 128 + s4 + 0] = a1;  ps2[nr * 128 + s4 + 0] = a2;
        ps1[nr * 128 + s4 + 1] = b1a; ps2[nr * 128 + s4 + 1] = b2a;
        ps1[nr * 128 + s4 + 2] = c1;  ps2[nr * 128 + s4 + 2] = c2;
        ps1[nr * 128 + s4 + 3] = d1;  ps2[nr * 128 + s4 + 3] = d2;
    }
    w1s[tid] = w1[tid];
    b1s[tid] = b1[tid];
    wkqs[tid] = g_wkq[tid];
    __syncthreads();
    if (tid < 128) {
        float s1 = 0.f, s2 = 0.f;
#pragma unroll
        for (int g = 0; g < 8; g++) { s1 += ps1[g * 128 + tid]; s2 += ps2[g * 128 + tid]; }
        float mu = s1 * (1.f / N_);
        float var = s2 * (1.f / N_) - mu * mu;
        float rs = rsqrtf(var + 1e-5f);
        muS[tid] = mu;
        rsS[tid] = rs;
        g_mu1[bk * S_ + s_base + tid] = mu;
        g_rs1[bk * S_ + s_base + tid] = rs;
    }
    __syncthreads();

    // ---- write pass ----
    __nv_bfloat16* hb = g_hb + (size_t)bk * BE;
    float accv[4] = {0.f, 0.f, 0.f, 0.f};
    float mus[4], rss[4];
#pragma unroll
    for (int si = 0; si < 4; si++) { mus[si] = muS[s4 + si]; rss[si] = rsS[s4 + si]; }

#pragma unroll
    for (int oct = 0; oct < 4; oct++) {
        int n0 = nr * 32 + oct * 8;
        float4 xv[8];
#pragma unroll
        for (int i = 0; i < 8; i++)
            xv[i] = *(const float4*)(xb + (size_t)(n0 + i) * (Kd * S_) + s4);
        float w1v[8], b1v[8], wkv[8];
#pragma unroll
        for (int i = 0; i < 8; i++) { w1v[i] = w1s[n0 + i]; b1v[i] = b1s[n0 + i]; wkv[i] = wkqs[n0 + i]; }
#pragma unroll
        for (int si = 0; si < 4; si++) {
            int s_glob = s_base + s4 + si;
            const float4* pep = (const float4*)(g_pe + (size_t)s_glob * N_ + n0);
            float4 pe0 = pep[0], pe1 = pep[1];
            float pev[8] = {pe0.x, pe0.y, pe0.z, pe0.w, pe1.x, pe1.y, pe1.z, pe1.w};
            uint32_t pk[4];
#pragma unroll
            for (int p = 0; p < 4; p++) {
                float x0 = ((const float*)&xv[2 * p])[si];
                float x1 = ((const float*)&xv[2 * p + 1])[si];
                float hv0 = (x0 - mus[si]) * rss[si] * w1v[2 * p]     + b1v[2 * p]     + pev[2 * p];
                float hv1 = (x1 - mus[si]) * rss[si] * w1v[2 * p + 1] + b1v[2 * p + 1] + pev[2 * p + 1];
                accv[si] += hv0 * wkv[2 * p] + hv1 * wkv[2 * p + 1];
                __nv_bfloat162 t = __floats2bfloat162_rn(hv0, hv1);
                pk[p] = *(uint32_t*)&t;
            }
            *(uint4*)(hb + (size_t)s_glob * N_ + n0) = make_uint4(pk[0], pk[1], pk[2], pk[3]);
        }
    }
#pragma unroll
    for (int si = 0; si < 4; si++) vp[nr * 128 + s4 + si] = accv[si];
    __syncthreads();
    if (tid < 128) {
        float s = 0.f;
#pragma unroll
        for (int g = 0; g < 8; g++) s += vp[g * 128 + tid];
        g_vcol[bk * 256 + s_base + tid] = s;
    }
}

// ---------------- qkv_mma: which=0 -> T=h.M ; which=1 -> Vt=Wv.h^T ---------
#define Q_A0   0
#define Q_A1   16384
#define Q_B0   32768
#define Q_B1   49152
#define Q_BIAS 65536
#define Q_SMEM 66560

__global__ void __launch_bounds__(256, 2)
qkv_mma(const float* __restrict__ vb_) {
    extern __shared__ char smem_dyn[];
    uint32_t sb = smem_u32(smem_dyn);
    int tid = threadIdx.x, lane = tid & 31, wid = tid >> 5;
    int wm = wid >> 2, wn = wid & 3;
    int m_base = wm * 64, n_base = wn * 32;

    int mt = blockIdx.x >> 1, nt = blockIdx.x & 1;
    int which = blockIdx.y, bk = blockIdx.z;

    const __nv_bfloat16* hb = g_hb + (size_t)bk * BE;
    const __nv_bfloat16 *Ag, *Bg;
    __nv_bfloat16* outp;
    if (which == 0) { Ag = hb + mt * 128 * 256;     Bg = g_Mb + nt * 128 * 256; outp = g_Tb + (size_t)bk * BE; }
    else            { Ag = g_wv + mt * 128 * 256;   Bg = hb + nt * 128 * 256;   outp = g_Vt + (size_t)bk * BE; }

    float* biass = (float*)(smem_dyn + Q_BIAS);
    if (tid < 256) biass[tid] = vb_[tid];

    float acc[4][4][4] = {};

    tile_cp(sb + Q_A0, Ag, 128, tid, 256);
    tile_cp(sb + Q_B0, Bg, 128, tid, 256);
    CP_COMMIT();

    for (int c = 0; c < 4; c++) {
        int cur = c & 1;
        if (c + 1 < 4) {
            tile_cp(sb + (cur ? Q_A0 : Q_A1), Ag + (c + 1) * 64, 128, tid, 256);
            tile_cp(sb + (cur ? Q_B0 : Q_B1), Bg + (c + 1) * 64, 128, tid, 256);
            CP_COMMIT();
            CP_WAIT1();
        } else {
            CP_WAIT0();
        }
        __syncthreads();
        uint32_t aB = sb + (cur ? Q_A1 : Q_A0);
        uint32_t bB = sb + (cur ? Q_B1 : Q_B0);
#pragma unroll
        for (int kk = 0; kk < 4; kk++) {
            int ksg = kk * 2;
            uint32_t a[4][4];
#pragma unroll
            for (int mi = 0; mi < 4; mi++)
                ldmat4(a[mi][0], a[mi][1], a[mi][2], a[mi][3], a_addr(aB, m_base + mi * 16, ksg, lane));
            uint32_t bfr[4][2];
#pragma unroll
            for (int nj = 0; nj < 2; nj++) {
                uint32_t r0, r1, r2, r3;
                ldmat4(r0, r1, r2, r3, b_addr(bB, n_base + nj * 16, ksg, lane));
                bfr[nj * 2][0] = r0;     bfr[nj * 2][1] = r1;
                bfr[nj * 2 + 1][0] = r2; bfr[nj * 2 + 1][1] = r3;
            }
#pragma unroll
            for (int mi = 0; mi < 4; mi++)
#pragma unroll
                for (int ni = 0; ni < 4; ni++)
                    mma16816(acc[mi][ni], a[mi], bfr[ni]);
        }
        __syncthreads();
    }

#pragma unroll
    for (int mi = 0; mi < 4; mi++) {
#pragma unroll
        for (int h = 0; h < 2; h++) {
            int rloc = m_base + mi * 16 + h * 8 + (lane >> 2);
            int grow = mt * 128 + rloc;
            float rb = (which == 1) ? biass[grow] : 0.f;
#pragma unroll
            for (int ni = 0; ni < 4; ni++) {
                int cloc = n_base + ni * 8 + (lane & 3) * 2;
                int gcol = nt * 128 + cloc;
                float v0 = acc[mi][ni][h * 2 + 0] + rb;
                float v1 = acc[mi][ni][h * 2 + 1] + rb;
                __nv_bfloat162 t = __floats2bfloat162_rn(v0, v1);
                *(uint32_t*)(outp + grow * 256 + gcol) = *(uint32_t*)&t;
            }
        }
    }
}

// ---------------- attn_mma: per (bk, 64-q tile), warps 32x64 ----------------
#define A_QS   0
#define A_BS   32768
#define A_PS   65536
#define A_RED  98304
#define A_FROW 99328
#define A_MU1  99584
#define A_RS1  99840
#define A_MU2  100096
#define A_RS2  100352
#define A_W1   100608
#define A_B1   101632
#define A_W2   102656
#define A_B2   103680
#define A_VC   104704
#define A_SMEM 105728

__global__ void __launch_bounds__(256, 2)
attn_mma(const float* __restrict__ x, float* __restrict__ out,
         const float* __restrict__ w2, const float* __restrict__ b2,
         const float* __restrict__ w1, const float* __restrict__ b1) {
    extern __shared__ char smem_dyn[];
    uint32_t sb = smem_u32(smem_dyn);
    int tid = threadIdx.x, lane = tid & 31, wid = tid >> 5;
    int wm = wid >> 2, wn = wid & 3;
    int q0 = blockIdx.x * 64;
    int bk = blockIdx.y;

    float* sRed  = (float*)(smem_dyn + A_RED);
    float* frowS = (float*)(smem_dyn + A_FROW);
    float* mu1s  = (float*)(smem_dyn + A_MU1);
    float* rs1s  = (float*)(smem_dyn + A_RS1);
    float* mu2s  = (float*)(smem_dyn + A_MU2);
    float* rs2s  = (float*)(smem_dyn + A_RS2);
    float* w1s   = (float*)(smem_dyn + A_W1);
    float* b1s   = (float*)(smem_dyn + A_B1);
    float* w2s   = (float*)(smem_dyn + A_W2);
    float* b2s   = (float*)(smem_dyn + A_B2);
    float* vcS   = (float*)(smem_dyn + A_VC);
    if (tid < 256) {
        w1s[tid] = w1[tid]; b1s[tid] = b1[tid];
        w2s[tid] = w2[tid]; b2s[tid] = b2[tid];
        vcS[tid] = g_vcol[bk * 256 + tid];
    }
    if (tid < 64)  { mu1s[tid] = g_mu1[bk * S_ + q0 + tid]; rs1s[tid] = g_rs1[bk * S_ + q0 + tid]; }

    const __nv_bfloat16* Qg = g_Tb + (size_t)bk * BE + q0 * 256;
    const __nv_bfloat16* Kg = g_hb + (size_t)bk * BE;
    const __nv_bfloat16* Vg = g_Vt + (size_t)bk * BE;

    float acc[2][8][4] = {};

    // ---- phase 1: logits = T . h^T ----
    for (int jc = 0; jc < 4; jc++)
        tile_cp(sb + A_QS + jc * 8192, Qg + jc * 64, 64, tid, 256);
    tile_cp(sb + A_BS, Kg, 256, tid, 256);
    CP_COMMIT();
    for (int jc = 0; jc < 4; jc++) {
        if (jc < 3) {
            tile_cp(sb + ((jc & 1) ? A_BS : A_PS), Kg + (jc + 1) * 64, 256, tid, 256);
            CP_COMMIT(); CP_WAIT1();
        } else CP_WAIT0();
        __syncthreads();
        uint32_t aB = sb + A_QS + jc * 8192;
        uint32_t bB = sb + ((jc & 1) ? A_PS : A_BS);
#pragma unroll
        for (int kk = 0; kk < 4; kk++) {
            int ksg = kk * 2;
            uint32_t a[2][4];
#pragma unroll
            for (int mi = 0; mi < 2; mi++)
                ldmat4(a[mi][0], a[mi][1], a[mi][2], a[mi][3], a_addr(aB, wm * 32 + mi * 16, ksg, lane));
#pragma unroll
            for (int nj = 0; nj < 4; nj++) {
                uint32_t r0, r1, r2, r3;
                ldmat4(r0, r1, r2, r3, b_addr(bB, wn * 64 + nj * 16, ksg, lane));
                uint32_t b0[2] = {r0, r1}, b1v[2] = {r2, r3};
#pragma unroll
                for (int mi = 0; mi < 2; mi++) {
                    mma16816(acc[mi][nj * 2],     a[mi], b0);
                    mma16816(acc[mi][nj * 2 + 1], a[mi], b1v);
                }
            }
        }
        __syncthreads();
    }

    // add vcol[k]
#pragma unroll
    for (int mi = 0; mi < 2; mi++)
#pragma unroll
        for (int ni = 0; ni < 8; ni++) {
            int k0 = wn * 64 + ni * 8 + (lane & 3) * 2;
            float v0 = vcS[k0], v1 = vcS[k0 + 1];
            acc[mi][ni][0] += v0; acc[mi][ni][1] += v1;
            acc[mi][ni][2] += v0; acc[mi][ni][3] += v1;
        }

    // prefetch V chunk0
    tile_cp(sb + A_BS, Vg, 256, tid, 256);
    CP_COMMIT();

    // ---- softmax ----
#pragma unroll
    for (int mi = 0; mi < 2; mi++)
#pragma unroll
        for (int h = 0; h < 2; h++) {
            float pm = -1e30f;
#pragma unroll
            for (int ni = 0; ni < 8; ni++) {
                pm = fmaxf(pm, acc[mi][ni][h * 2 + 0]);
                pm = fmaxf(pm, acc[mi][ni][h * 2 + 1]);
            }
            pm = fmaxf(pm, __shfl_xor_sync(0xffffffffu, pm, 1));
            pm = fmaxf(pm, __shfl_xor_sync(0xffffffffu, pm, 2));
            if ((lane & 3) == 0)
                sRed[wn * 64 + wm * 32 + mi * 16 + h * 8 + (lane >> 2)] = pm;
        }
    __syncthreads();
    float rm[2][2];
#pragma unroll
    for (int mi = 0; mi < 2; mi++)
#pragma unroll
        for (int h = 0; h < 2; h++) {
            int r = wm * 32 + mi * 16 + h * 8 + (lane >> 2);
            rm[mi][h] = fmaxf(fmaxf(sRed[r], sRed[64 + r]), fmaxf(sRed[128 + r], sRed[192 + r]));
        }
    __syncthreads();
#pragma unroll
    for (int mi = 0; mi < 2; mi++)
#pragma unroll
        for (int h = 0; h < 2; h++) {
            int r = wm * 32 + mi * 16 + h * 8 + (lane >> 2);
            float ps = 0.f;
#pragma unroll
            for (int ni = 0; ni < 8; ni++) {
                float e0 = __expf(acc[mi][ni][h * 2 + 0] - rm[mi][h]);
                float e1 = __expf(acc[mi][ni][h * 2 + 1] - rm[mi][h]);
                ps += e0 + e1;
                __nv_bfloat162 t = __floats2bfloat162_rn(e0, e1);
                int cl = (wn * 64 + ni * 8 + (lane & 3) * 2) & 63;
                int cb = cl * 2;
                uint32_t addr = sb + A_PS + wn * 8192 + r * 128
                              + ((((uint32_t)cb >> 4) ^ (uint32_t)(r & 7)) << 4) + (cb & 15);
                asm volatile("st.shared.b32 [%0], %1;" :: "r"(addr), "r"(*(uint32_t*)&t));
            }
            ps += __shfl_xor_sync(0xffffffffu, ps, 1);
            ps += __shfl_xor_sync(0xffffffffu, ps, 2);
            if ((lane & 3) == 0) sRed[wn * 64 + r] = ps;
        }
    __syncthreads();
    if (tid < 64)
        frowS[tid] = SCALE / (sRed[tid] + sRed[64 + tid] + sRed[128 + tid] + sRed[192 + tid]);
#pragma unroll
    for (int mi = 0; mi < 2; mi++)
#pragma unroll
        for (int ni = 0; ni < 8; ni++)
#pragma unroll
            for (int j = 0; j < 4; j++) acc[mi][ni][j] = 0.f;
    __syncthreads();

    // ---- phase 2: O = expP . Vt^T ----
    for (int sc = 0; sc < 4; sc++) {
        if (sc < 3) {
            tile_cp(sb + ((sc & 1) ? A_BS : A_QS), Vg + (sc + 1) * 64, 256, tid, 256);
            CP_COMMIT(); CP_WAIT1();
        } else CP_WAIT0();
        __syncthreads();
        uint32_t aB = sb + A_PS + sc * 8192;
        uint32_t bB = sb + ((sc & 1) ? A_QS : A_BS);
#pragma unroll
        for (int kk = 0; kk < 4; kk++) {
            int ksg = kk * 2;
            uint32_t a[2][4];
#pragma unroll
            for (int mi = 0; mi < 2; mi++)
                ldmat4(a[mi][0], a[mi][1], a[mi][2], a[mi][3], a_addr(aB, wm * 32 + mi * 16, ksg, lane));
#pragma unroll
            for (int nj = 0; nj < 4; nj++) {
                uint32_t r0, r1, r2, r3;
                ldmat4(r0, r1, r2, r3, b_addr(bB, wn * 64 + nj * 16, ksg, lane));
                uint32_t b0[2] = {r0, r1}, b1v[2] = {r2, r3};
#pragma unroll
                for (int mi = 0; mi < 2; mi++) {
                    mma16816(acc[mi][nj * 2],     a[mi], b0);
                    mma16816(acc[mi][nj * 2 + 1], a[mi], b1v);
                }
            }
        }
        __syncthreads();
    }

    // ---- epilogue ----
    float* Os = (float*)smem_dyn;   // [64][257]
#pragma unroll
    for (int mi = 0; mi < 2; mi++)
#pragma unroll
        for (int h = 0; h < 2; h++) {
            int r = wm * 32 + mi * 16 + h * 8 + (lane >> 2);
            float fr = frowS[r];
#pragma unroll
            for (int ni = 0; ni < 8; ni++) {
                int d = wn * 64 + ni * 8 + (lane & 3) * 2;
                Os[r * 257 + d]     = acc[mi][ni][h * 2 + 0] * fr;
                Os[r * 257 + d + 1] = acc[mi][ni][h * 2 + 1] * fr;
            }
        }
    __syncthreads();

    int b = bk >> 7, kk2 = bk & 127;
    const float* xb = x   + (size_t)b * (N_ * Kd * S_) + kk2 * S_ + q0;
    float*       ob = out + (size_t)b * (N_ * Kd * S_) + kk2 * S_ + q0;

#pragma unroll 4
    for (int it = 0; it < 64; it++) {
        int idx = it * 256 + tid;
        int qi = idx & 63, d = idx >> 6;
        float xv = xb[d * (Kd * S_) + qi];
        float hv = (xv - mu1s[qi]) * rs1s[qi] * w1s[d] + b1s[d] + g_peT[d * S_ + q0 + qi];
        Os[qi * 257 + d] += hv;
    }
    __syncthreads();

    {
        int r = tid >> 2, sub = tid & 3;
        float s1 = 0.f, s2 = 0.f;
#pragma unroll 8
        for (int j = 0; j < 64; j++) {
            float v = Os[r * 257 + sub * 64 + j];
            s1 += v; s2 += v * v;
        }
        s1 += __shfl_xor_sync(0xffffffffu, s1, 1); s2 += __shfl_xor_sync(0xffffffffu, s2, 1);
        s1 += __shfl_xor_sync(0xffffffffu, s1, 2); s2 += __shfl_xor_sync(0xffffffffu, s2, 2);
        if (sub == 0) {
            float mu = s1 * (1.f / N_);
            float var = s2 * (1.f / N_) - mu * mu;
            mu2s[r] = mu;
            rs2s[r] = rsqrtf(var + 1e-5f);
        }
    }
    __syncthreads();

#pragma unroll 4
    for (int it = 0; it < 64; it++) {
        int idx = it * 256 + tid;
        int qi = idx & 63, d = idx >> 6;
        float v = Os[qi * 257 + d];
        float o = (v - mu2s[qi]) * rs2s[qi] * w2s[d] + b2s[d] + xb[d * (Kd * S_) + qi];
        ob[d * (Kd * S_) + qi] = o;
    }
}

extern "C" void kernel_launch(void* const* d_in, const int* in_sizes, int n_in,
                              void* d_out, int out_size) {
    const float* x    = (const float*)d_in[0];
    const float* ln1w = (const float*)d_in[1];
    const float* ln1b = (const float*)d_in[2];
    const float* qw   = (const float*)d_in[3];
    const float* qb   = (const float*)d_in[4];
    const float* kw   = (const float*)d_in[5];
    const float* kb   = (const float*)d_in[6];
    const float* vw   = (const float*)d_in[7];
    const float* vb   = (const float*)d_in[8];
    const float* w2   = (const float*)d_in[9];
    const float* b2   = (const float*)d_in[10];
    float* out = (float*)d_out;

    cudaFuncSetAttribute(qkv_mma,  cudaFuncAttributeMaxDynamicSharedMemorySize, Q_SMEM);
    cudaFuncSetAttribute(attn_mma, cudaFuncAttributeMaxDynamicSharedMemorySize, A_SMEM);

    setup_kernel<<<256, 256>>>(qw, kw, qb, vw);
    ln1_kernel<<<dim3(BKt, 2), 256>>>(x, ln1w, ln1b);
    qkv_mma<<<dim3(4, 2, BKt), 256, Q_SMEM>>>(vb);
    attn_mma<<<dim3(4, BKt), 256, A_SMEM>>>(x, out, w2, b2, ln1w, ln1b);
}

// round 15
// speedup vs baseline: 1.1295x; 1.1086x over previous
#include <cuda_runtime.h>
#include <cuda_bf16.h>
#include <math.h>
#include <stdint.h>

#define B_   4
#define N_   256
#define Kd   128
#define S_   256
#define BKt  512
#define BE   65536
#define SCALE 0.0625f

__device__ __align__(256) float          g_pe [S_ * N_];      // [s][n]
__device__ __align__(256) float          g_peT[N_ * S_];      // [n][s]
__device__ __align__(256) float          g_mu1[BKt * S_];
__device__ __align__(256) float          g_rs1[BKt * S_];
__device__ __align__(256) float          g_wkq[N_];
__device__ __align__(256) float          g_vcol[BKt * S_];
__device__ __align__(256) __nv_bfloat16  g_hb[BKt * BE];
__device__ __align__(256) __nv_bfloat16  g_Tb[BKt * BE];
__device__ __align__(256) __nv_bfloat16  g_Vt[BKt * BE];
__device__ __align__(256) __nv_bfloat16  g_wv[N_ * N_];
__device__ __align__(256) __nv_bfloat16  g_Mb[N_ * N_];

// ---------------- helpers ----------------
__device__ __forceinline__ uint32_t smem_u32(const void* p) {
    uint32_t a;
    asm("{ .reg .u64 t; cvta.to.shared.u64 t, %1; cvt.u32.u64 %0, t; }" : "=r"(a) : "l"(p));
    return a;
}
__device__ __forceinline__ void cpasync16(uint32_t dst, const void* src) {
    asm volatile("cp.async.cg.shared.global [%0], [%1], 16;" :: "r"(dst), "l"(src));
}
#define CP_COMMIT() asm volatile("cp.async.commit_group;" ::: "memory")
#define CP_WAIT0()  asm volatile("cp.async.wait_group 0;" ::: "memory")
#define CP_WAIT1()  asm volatile("cp.async.wait_group 1;" ::: "memory")

__device__ __forceinline__ void ldmat4(uint32_t& r0, uint32_t& r1, uint32_t& r2, uint32_t& r3, uint32_t addr) {
    asm volatile("ldmatrix.sync.aligned.m8n8.x4.shared.b16 {%0,%1,%2,%3}, [%4];"
                 : "=r"(r0), "=r"(r1), "=r"(r2), "=r"(r3) : "r"(addr));
}
__device__ __forceinline__ void mma16816(float* d, const uint32_t* a, const uint32_t* b) {
    asm volatile("mma.sync.aligned.m16n8k16.row.col.f32.bf16.bf16.f32 "
                 "{%0,%1,%2,%3},{%4,%5,%6,%7},{%8,%9},{%0,%1,%2,%3};"
                 : "+f"(d[0]), "+f"(d[1]), "+f"(d[2]), "+f"(d[3])
                 : "r"(a[0]), "r"(a[1]), "r"(a[2]), "r"(a[3]), "r"(b[0]), "r"(b[1]));
}
__device__ __forceinline__ void tile_cp(uint32_t dst, const __nv_bfloat16* __restrict__ src,
                                        int rows, int tid, int nthr) {
    int total = rows * 8;
    for (int u = tid; u < total; u += nthr) {
        int row = u >> 3, seg = u & 7;
        cpasync16(dst + row * 128 + (((uint32_t)(seg ^ (row & 7))) << 4), src + row * 256 + seg * 8);
    }
}
__device__ __forceinline__ uint32_t a_addr(uint32_t base, int m0, int ksg, int lane) {
    int row = m0 + (lane & 15);
    int seg = ksg + (lane >> 4);
    return base + row * 128 + (((uint32_t)(seg ^ (row & 7))) << 4);
}
__device__ __forceinline__ uint32_t b_addr(uint32_t base, int n0, int ksg, int lane) {
    int row = n0 + ((lane >> 4) << 3) + (lane & 7);
    int seg = ksg + ((lane >> 3) & 1);
    return base + row * 128 + (((uint32_t)(seg ^ (row & 7))) << 4);
}

// ---------------------------------------------------------------------------
__global__ void __launch_bounds__(256) setup_kernel(const float* __restrict__ qw,
                                                    const float* __restrict__ kw,
                                                    const float* __restrict__ qb,
                                                    const float* __restrict__ vw) {
    __shared__ float kcol[256];
    __shared__ float part[256];
    int m = blockIdx.x, n = threadIdx.x;

    float freq = __expf(-(float)(n & ~1) * (9.210340371976184f / 256.0f));
    float a = (float)m * freq;
    float v = (n & 1) ? cosf(a) : sinf(a);
    g_pe [m * N_ + n] = v;
    g_peT[n * S_ + m] = v;

    g_wv[m * 256 + n] = __float2bfloat16(vw[m * 256 + n]);

    kcol[n] = kw[n * 256 + m];
    part[n] = qb[n] * kcol[n];
    __syncthreads();
    if (n == 0) {
        float s = 0.f;
        for (int i = 0; i < 256; i++) s += part[i];
        g_wkq[m] = s;
    }
    float s = 0.f;
#pragma unroll 4
    for (int i = 0; i < 256; i++) s += kcol[i] * qw[i * 256 + n];
    g_Mb[m * 256 + n] = __float2bfloat16(s);
}

// LN1 stats + bf16 h + fused vcol. Grid (bk, 2).
__global__ void __launch_bounds__(256) ln1_kernel(const float* __restrict__ x,
                                                  const float* __restrict__ w1,
                                                  const float* __restrict__ b1) {
    __shared__ float ps1[8 * 128], ps2[8 * 128];
    __shared__ float muS[128], rsS[128];
    __shared__ float w1s[256], b1s[256], wkqs[256];
    __shared__ float vp[8 * 128];
    int bk = blockIdx.x, half = blockIdx.y;
    int b = bk >> 7, k = bk & 127;
    int tid = threadIdx.x;
    int s_base = half * 128;
    const float* xb = x + ((size_t)b * N_ * Kd + k) * S_ + s_base;
    int sq = tid & 31;
    int nr = tid >> 5;
    int s4 = sq * 4;

    {
        float a1 = 0.f, a2 = 0.f, b1a = 0.f, b2a = 0.f, c1 = 0.f, c2 = 0.f, d1 = 0.f, d2 = 0.f;
        const float* xp = xb + (size_t)(nr * 32) * (Kd * S_) + s4;
#pragma unroll 8
        for (int i = 0; i < 32; i++) {
            float4 v = *(const float4*)(xp + (size_t)i * (Kd * S_));
            a1 += v.x; a2 += v.x * v.x;
            b1a += v.y; b2a += v.y * v.y;
            c1 += v.z; c2 += v.z * v.z;
            d1 += v.w; d2 += v.w * v.w;
        }
        ps1[nr * 128 + s4 + 0] = a1;  ps2[nr * 128 + s4 + 0] = a2;
        ps1[nr * 128 + s4 + 1] = b1a; ps2[nr * 128 + s4 + 1] = b2a;
        ps1[nr * 128 + s4 + 2] = c1;  ps2[nr * 128 + s4 + 2] = c2;
        ps1[nr * 128 + s4 + 3] = d1;  ps2[nr * 128 + s4 + 3] = d2;
    }
    w1s[tid] = w1[tid];
    b1s[tid] = b1[tid];
    wkqs[tid] = g_wkq[tid];
    __syncthreads();
    if (tid < 128) {
        float s1 = 0.f, s2 = 0.f;
#pragma unroll
        for (int g = 0; g < 8; g++) { s1 += ps1[g * 128 + tid]; s2 += ps2[g * 128 + tid]; }
        float mu = s1 * (1.f / N_);
        float var = s2 * (1.f / N_) - mu * mu;
        float rs = rsqrtf(var + 1e-5f);
        muS[tid] = mu;
        rsS[tid] = rs;
        g_mu1[bk * S_ + s_base + tid] = mu;
        g_rs1[bk * S_ + s_base + tid] = rs;
    }
    __syncthreads();

    __nv_bfloat16* hb = g_hb + (size_t)bk * BE;
    float accv[4] = {0.f, 0.f, 0.f, 0.f};
    float mus[4], rss[4];
#pragma unroll
    for (int si = 0; si < 4; si++) { mus[si] = muS[s4 + si]; rss[si] = rsS[s4 + si]; }

#pragma unroll
    for (int oct = 0; oct < 4; oct++) {
        int n0 = nr * 32 + oct * 8;
        float4 xv[8];
#pragma unroll
        for (int i = 0; i < 8; i++)
            xv[i] = *(const float4*)(xb + (size_t)(n0 + i) * (Kd * S_) + s4);
        float w1v[8], b1v[8], wkv[8];
#pragma unroll
        for (int i = 0; i < 8; i++) { w1v[i] = w1s[n0 + i]; b1v[i] = b1s[n0 + i]; wkv[i] = wkqs[n0 + i]; }
#pragma unroll
        for (int si = 0; si < 4; si++) {
            int s_glob = s_base + s4 + si;
            const float4* pep = (const float4*)(g_pe + (size_t)s_glob * N_ + n0);
            float4 pe0 = pep[0], pe1 = pep[1];
            float pev[8] = {pe0.x, pe0.y, pe0.z, pe0.w, pe1.x, pe1.y, pe1.z, pe1.w};
            uint32_t pk[4];
#pragma unroll
            for (int p = 0; p < 4; p++) {
                float x0 = ((const float*)&xv[2 * p])[si];
                float x1 = ((const float*)&xv[2 * p + 1])[si];
                float hv0 = (x0 - mus[si]) * rss[si] * w1v[2 * p]     + b1v[2 * p]     + pev[2 * p];
                float hv1 = (x1 - mus[si]) * rss[si] * w1v[2 * p + 1] + b1v[2 * p + 1] + pev[2 * p + 1];
                accv[si] += hv0 * wkv[2 * p] + hv1 * wkv[2 * p + 1];
                __nv_bfloat162 t = __floats2bfloat162_rn(hv0, hv1);
                pk[p] = *(uint32_t*)&t;
            }
            *(uint4*)(hb + (size_t)s_glob * N_ + n0) = make_uint4(pk[0], pk[1], pk[2], pk[3]);
        }
    }
#pragma unroll
    for (int si = 0; si < 4; si++) vp[nr * 128 + s4 + si] = accv[si];
    __syncthreads();
    if (tid < 128) {
        float s = 0.f;
#pragma unroll
        for (int g = 0; g < 8; g++) s += vp[g * 128 + tid];
        g_vcol[bk * 256 + s_base + tid] = s;
    }
}

// ---------------- qkv_mma ----------------
#define Q_A0   0
#define Q_A1   16384
#define Q_B0   32768
#define Q_B1   49152
#define Q_BIAS 65536
#define Q_SMEM 66560

__global__ void __launch_bounds__(256, 2)
qkv_mma(const float* __restrict__ vb_) {
    extern __shared__ char smem_dyn[];
    uint32_t sb = smem_u32(smem_dyn);
    int tid = threadIdx.x, lane = tid & 31, wid = tid >> 5;
    int wm = wid >> 2, wn = wid & 3;
    int m_base = wm * 64, n_base = wn * 32;

    int mt = blockIdx.x >> 1, nt = blockIdx.x & 1;
    int which = blockIdx.y, bk = blockIdx.z;

    const __nv_bfloat16* hb = g_hb + (size_t)bk * BE;
    const __nv_bfloat16 *Ag, *Bg;
    __nv_bfloat16* outp;
    if (which == 0) { Ag = hb + mt * 128 * 256;     Bg = g_Mb + nt * 128 * 256; outp = g_Tb + (size_t)bk * BE; }
    else            { Ag = g_wv + mt * 128 * 256;   Bg = hb + nt * 128 * 256;   outp = g_Vt + (size_t)bk * BE; }

    float* biass = (float*)(smem_dyn + Q_BIAS);
    if (tid < 256) biass[tid] = vb_[tid];

    float acc[4][4][4] = {};

    tile_cp(sb + Q_A0, Ag, 128, tid, 256);
    tile_cp(sb + Q_B0, Bg, 128, tid, 256);
    CP_COMMIT();

    for (int c = 0; c < 4; c++) {
        int cur = c & 1;
        if (c + 1 < 4) {
            tile_cp(sb + (cur ? Q_A0 : Q_A1), Ag + (c + 1) * 64, 128, tid, 256);
            tile_cp(sb + (cur ? Q_B0 : Q_B1), Bg + (c + 1) * 64, 128, tid, 256);
            CP_COMMIT();
            CP_WAIT1();
        } else {
            CP_WAIT0();
        }
        __syncthreads();
        uint32_t aB = sb + (cur ? Q_A1 : Q_A0);
        uint32_t bB = sb + (cur ? Q_B1 : Q_B0);
#pragma unroll
        for (int kk = 0; kk < 4; kk++) {
            int ksg = kk * 2;
            uint32_t a[4][4];
#pragma unroll
            for (int mi = 0; mi < 4; mi++)
                ldmat4(a[mi][0], a[mi][1], a[mi][2], a[mi][3], a_addr(aB, m_base + mi * 16, ksg, lane));
            uint32_t bfr[4][2];
#pragma unroll
            for (int nj = 0; nj < 2; nj++) {
                uint32_t r0, r1, r2, r3;
                ldmat4(r0, r1, r2, r3, b_addr(bB, n_base + nj * 16, ksg, lane));
                bfr[nj * 2][0] = r0;     bfr[nj * 2][1] = r1;
                bfr[nj * 2 + 1][0] = r2; bfr[nj * 2 + 1][1] = r3;
            }
#pragma unroll
            for (int mi = 0; mi < 4; mi++)
#pragma unroll
                for (int ni = 0; ni < 4; ni++)
                    mma16816(acc[mi][ni], a[mi], bfr[ni]);
        }
        __syncthreads();
    }

#pragma unroll
    for (int mi = 0; mi < 4; mi++) {
#pragma unroll
        for (int h = 0; h < 2; h++) {
            int rloc = m_base + mi * 16 + h * 8 + (lane >> 2);
            int grow = mt * 128 + rloc;
            float rb = (which == 1) ? biass[grow] : 0.f;
#pragma unroll
            for (int ni = 0; ni < 4; ni++) {
                int cloc = n_base + ni * 8 + (lane & 3) * 2;
                int gcol = nt * 128 + cloc;
                float v0 = acc[mi][ni][h * 2 + 0] + rb;
                float v1 = acc[mi][ni][h * 2 + 1] + rb;
                __nv_bfloat162 t = __floats2bfloat162_rn(v0, v1);
                *(uint32_t*)(outp + grow * 256 + gcol) = *(uint32_t*)&t;
            }
        }
    }
}

// ---------------- attn_mma ----------------
#define A_QS   0
#define A_BS   32768
#define A_PS   65536
#define A_RED  98304
#define A_FROW 99328
#define A_MU1  99584
#define A_RS1  99840
#define A_MU2  100096
#define A_RS2  100352
#define A_W1   100608
#define A_B1   101632
#define A_W2   102656
#define A_B2   103680
#define A_VC   104704
#define A_SMEM 105728

__global__ void __launch_bounds__(256, 2)
attn_mma(const float* __restrict__ x, float* __restrict__ out,
         const float* __restrict__ w2, const float* __restrict__ b2,
         const float* __restrict__ w1, const float* __restrict__ b1) {
    extern __shared__ char smem_dyn[];
    uint32_t sb = smem_u32(smem_dyn);
    int tid = threadIdx.x, lane = tid & 31, wid = tid >> 5;
    int wm = wid >> 2, wn = wid & 3;
    int q0 = blockIdx.x * 64;
    int bk = blockIdx.y;

    float* sRed  = (float*)(smem_dyn + A_RED);
    float* frowS = (float*)(smem_dyn + A_FROW);
    float* mu1s  = (float*)(smem_dyn + A_MU1);
    float* rs1s  = (float*)(smem_dyn + A_RS1);
    float* mu2s  = (float*)(smem_dyn + A_MU2);
    float* rs2s  = (float*)(smem_dyn + A_RS2);
    float* w1s   = (float*)(smem_dyn + A_W1);
    float* b1s   = (float*)(smem_dyn + A_B1);
    float* w2s   = (float*)(smem_dyn + A_W2);
    float* b2s   = (float*)(smem_dyn + A_B2);
    float* vcS   = (float*)(smem_dyn + A_VC);
    if (tid < 256) {
        w1s[tid] = w1[tid]; b1s[tid] = b1[tid];
        w2s[tid] = w2[tid]; b2s[tid] = b2[tid];
        vcS[tid] = g_vcol[bk * 256 + tid];
    }
    if (tid < 64)  { mu1s[tid] = g_mu1[bk * S_ + q0 + tid]; rs1s[tid] = g_rs1[bk * S_ + q0 + tid]; }

    const __nv_bfloat16* Qg = g_Tb + (size_t)bk * BE + q0 * 256;
    const __nv_bfloat16* Kg = g_hb + (size_t)bk * BE;
    const __nv_bfloat16* Vg = g_Vt + (size_t)bk * BE;

    float acc[2][8][4] = {};

    // ---- phase 1: logits = T . h^T ----
    for (int jc = 0; jc < 4; jc++)
        tile_cp(sb + A_QS + jc * 8192, Qg + jc * 64, 64, tid, 256);
    tile_cp(sb + A_BS, Kg, 256, tid, 256);
    CP_COMMIT();
    for (int jc = 0; jc < 4; jc++) {
        if (jc < 3) {
            tile_cp(sb + ((jc & 1) ? A_BS : A_PS), Kg + (jc + 1) * 64, 256, tid, 256);
            CP_COMMIT(); CP_WAIT1();
        } else CP_WAIT0();
        __syncthreads();
        uint32_t aB = sb + A_QS + jc * 8192;
        uint32_t bB = sb + ((jc & 1) ? A_PS : A_BS);
#pragma unroll
        for (int kk = 0; kk < 4; kk++) {
            int ksg = kk * 2;
            uint32_t a[2][4];
#pragma unroll
            for (int mi = 0; mi < 2; mi++)
                ldmat4(a[mi][0], a[mi][1], a[mi][2], a[mi][3], a_addr(aB, wm * 32 + mi * 16, ksg, lane));
#pragma unroll
            for (int nj = 0; nj < 4; nj++) {
                uint32_t r0, r1, r2, r3;
                ldmat4(r0, r1, r2, r3, b_addr(bB, wn * 64 + nj * 16, ksg, lane));
                uint32_t b0[2] = {r0, r1}, b1v[2] = {r2, r3};
#pragma unroll
                for (int mi = 0; mi < 2; mi++) {
                    mma16816(acc[mi][nj * 2],     a[mi], b0);
                    mma16816(acc[mi][nj * 2 + 1], a[mi], b1v);
                }
            }
        }
        __syncthreads();
    }

    // add vcol[k]
#pragma unroll
    for (int mi = 0; mi < 2; mi++)
#pragma unroll
        for (int ni = 0; ni < 8; ni++) {
            int k0 = wn * 64 + ni * 8 + (lane & 3) * 2;
            float v0 = vcS[k0], v1 = vcS[k0 + 1];
            acc[mi][ni][0] += v0; acc[mi][ni][1] += v1;
            acc[mi][ni][2] += v0; acc[mi][ni][3] += v1;
        }

    // prefetch V chunk0
    tile_cp(sb + A_BS, Vg, 256, tid, 256);
    CP_COMMIT();

    // ---- softmax ----
#pragma unroll
    for (int mi = 0; mi < 2; mi++)
#pragma unroll
        for (int h = 0; h < 2; h++) {
            float pm = -1e30f;
#pragma unroll
            for (int ni = 0; ni < 8; ni++) {
                pm = fmaxf(pm, acc[mi][ni][h * 2 + 0]);
                pm = fmaxf(pm, acc[mi][ni][h * 2 + 1]);
            }
            pm = fmaxf(pm, __shfl_xor_sync(0xffffffffu, pm, 1));
            pm = fmaxf(pm, __shfl_xor_sync(0xffffffffu, pm, 2));
            if ((lane & 3) == 0)
                sRed[wn * 64 + wm * 32 + mi * 16 + h * 8 + (lane >> 2)] = pm;
        }
    __syncthreads();
    float rm[2][2];
#pragma unroll
    for (int mi = 0; mi < 2; mi++)
#pragma unroll
        for (int h = 0; h < 2; h++) {
            int r = wm * 32 + mi * 16 + h * 8 + (lane >> 2);
            rm[mi][h] = fmaxf(fmaxf(sRed[r], sRed[64 + r]), fmaxf(sRed[128 + r], sRed[192 + r]));
        }
    __syncthreads();
#pragma unroll
    for (int mi = 0; mi < 2; mi++)
#pragma unroll
        for (int h = 0; h < 2; h++) {
            int r = wm * 32 + mi * 16 + h * 8 + (lane >> 2);
            float ps = 0.f;
#pragma unroll
            for (int ni = 0; ni < 8; ni++) {
                float e0 = __expf(acc[mi][ni][h * 2 + 0] - rm[mi][h]);
                float e1 = __expf(acc[mi][ni][h * 2 + 1] - rm[mi][h]);
                ps += e0 + e1;
                __nv_bfloat162 t = __floats2bfloat162_rn(e0, e1);
                int cl = (wn * 64 + ni * 8 + (lane & 3) * 2) & 63;
                int cb = cl * 2;
                uint32_t addr = sb + A_PS + wn * 8192 + r * 128
                              + ((((uint32_t)cb >> 4) ^ (uint32_t)(r & 7)) << 4) + (cb & 15);
                asm volatile("st.shared.b32 [%0], %1;" :: "r"(addr), "r"(*(uint32_t*)&t));
            }
            ps += __shfl_xor_sync(0xffffffffu, ps, 1);
            ps += __shfl_xor_sync(0xffffffffu, ps, 2);
            if ((lane & 3) == 0) sRed[wn * 64 + r] = ps;
        }
    __syncthreads();
    if (tid < 64)
        frowS[tid] = SCALE / (sRed[tid] + sRed[64 + tid] + sRed[128 + tid] + sRed[192 + tid]);
#pragma unroll
    for (int mi = 0; mi < 2; mi++)
#pragma unroll
        for (int ni = 0; ni < 8; ni++)
#pragma unroll
            for (int j = 0; j < 4; j++) acc[mi][ni][j] = 0.f;
    __syncthreads();

    // ---- phase 2: O = expP . Vt^T ----
    for (int sc = 0; sc < 4; sc++) {
        if (sc < 3) {
            tile_cp(sb + ((sc & 1) ? A_BS : A_QS), Vg + (sc + 1) * 64, 256, tid, 256);
            CP_COMMIT(); CP_WAIT1();
        } else CP_WAIT0();
        __syncthreads();
        uint32_t aB = sb + A_PS + sc * 8192;
        uint32_t bB = sb + ((sc & 1) ? A_QS : A_BS);
#pragma unroll
        for (int kk = 0; kk < 4; kk++) {
            int ksg = kk * 2;
            uint32_t a[2][4];
#pragma unroll
            for (int mi = 0; mi < 2; mi++)
                ldmat4(a[mi][0], a[mi][1], a[mi][2], a[mi][3], a_addr(aB, wm * 32 + mi * 16, ksg, lane));
#pragma unroll
            for (int nj = 0; nj < 4; nj++) {
                uint32_t r0, r1, r2, r3;
                ldmat4(r0, r1, r2, r3, b_addr(bB, wn * 64 + nj * 16, ksg, lane));
                uint32_t b0[2] = {r0, r1}, b1v[2] = {r2, r3};
#pragma unroll
                for (int mi = 0; mi < 2; mi++) {
                    mma16816(acc[mi][nj * 2],     a[mi], b0);
                    mma16816(acc[mi][nj * 2 + 1], a[mi], b1v);
                }
            }
        }
        __syncthreads();
    }

    // ---- epilogue (vectorized global traffic) ----
    float* Os = (float*)smem_dyn;   // [64][257]
#pragma unroll
    for (int mi = 0; mi < 2; mi++)
#pragma unroll
        for (int h = 0; h < 2; h++) {
            int r = wm * 32 + mi * 16 + h * 8 + (lane >> 2);
            float fr = frowS[r];
#pragma unroll
            for (int ni = 0; ni < 8; ni++) {
                int d = wn * 64 + ni * 8 + (lane & 3) * 2;
                Os[r * 257 + d]     = acc[mi][ni][h * 2 + 0] * fr;
                Os[r * 257 + d + 1] = acc[mi][ni][h * 2 + 1] * fr;
            }
        }
    __syncthreads();

    int b = bk >> 7, kk2 = bk & 127;
    const float* xb = x   + (size_t)b * (N_ * Kd * S_) + kk2 * S_ + q0;
    float*       ob = out + (size_t)b * (N_ * Kd * S_) + kk2 * S_ + q0;

    // loop1: Os[qi][d] += h recomputed; float4 over qi (16 iters of 4-qi blocks)
    {
        int qb4 = (tid & 15) * 4;          // qi base
        int d0  = tid >> 4;                // d row base (16 rows per iter)
#pragma unroll
        for (int it = 0; it < 16; it++) {
            int d = it * 16 + d0;
            float4 xv = *(const float4*)(xb + (size_t)d * (Kd * S_) + qb4);
            float4 pe = *(const float4*)(g_peT + (size_t)d * S_ + q0 + qb4);
            float w1v = w1s[d], b1v = b1s[d];
            Os[(qb4 + 0) * 257 + d] += (xv.x - mu1s[qb4 + 0]) * rs1s[qb4 + 0] * w1v + b1v + pe.x;
            Os[(qb4 + 1) * 257 + d] += (xv.y - mu1s[qb4 + 1]) * rs1s[qb4 + 1] * w1v + b1v + pe.y;
            Os[(qb4 + 2) * 257 + d] += (xv.z - mu1s[qb4 + 2]) * rs1s[qb4 + 2] * w1v + b1v + pe.z;
            Os[(qb4 + 3) * 257 + d] += (xv.w - mu1s[qb4 + 3]) * rs1s[qb4 + 3] * w1v + b1v + pe.w;
        }
    }
    __syncthreads();

    // LN2 stats: 4 threads per row
    {
        int r = tid >> 2, sub = tid & 3;
        float s1 = 0.f, s2 = 0.f;
#pragma unroll 8
        for (int j = 0; j < 64; j++) {
            float v = Os[r * 257 + sub * 64 + j];
            s1 += v; s2 += v * v;
        }
        s1 += __shfl_xor_sync(0xffffffffu, s1, 1); s2 += __shfl_xor_sync(0xffffffffu, s2, 1);
        s1 += __shfl_xor_sync(0xffffffffu, s1, 2); s2 += __shfl_xor_sync(0xffffffffu, s2, 2);
        if (sub == 0) {
            float mu = s1 * (1.f / N_);
            float var = s2 * (1.f / N_) - mu * mu;
            mu2s[r] = mu;
            rs2s[r] = rsqrtf(var + 1e-5f);
        }
    }
    __syncthreads();

    // loop3: normalize + x + store; float4 over qi
    {
        int qb4 = (tid & 15) * 4;
        int d0  = tid >> 4;
#pragma unroll
        for (int it = 0; it < 16; it++) {
            int d = it * 16 + d0;
            float4 xv = *(const float4*)(xb + (size_t)d * (Kd * S_) + qb4);
            float w2v = w2s[d], b2v = b2s[d];
            float4 o;
            o.x = (Os[(qb4 + 0) * 257 + d] - mu2s[qb4 + 0]) * rs2s[qb4 + 0] * w2v + b2v + xv.x;
            o.y = (Os[(qb4 + 1) * 257 + d] - mu2s[qb4 + 1]) * rs2s[qb4 + 1] * w2v + b2v + xv.y;
            o.z = (Os[(qb4 + 2) * 257 + d] - mu2s[qb4 + 2]) * rs2s[qb4 + 2] * w2v + b2v + xv.z;
            o.w = (Os[(qb4 + 3) * 257 + d] - mu2s[qb4 + 3]) * rs2s[qb4 + 3] * w2v + b2v + xv.w;
            *(float4*)(ob + (size_t)d * (Kd * S_) + qb4) = o;
        }
    }
}

extern "C" void kernel_launch(void* const* d_in, const int* in_sizes, int n_in,
                              void* d_out, int out_size) {
    const float* x    = (const float*)d_in[0];
    const float* ln1w = (const float*)d_in[1];
    const float* ln1b = (const float*)d_in[2];
    const float* qw   = (const float*)d_in[3];
    const float* qb   = (const float*)d_in[4];
    const float* kw   = (const float*)d_in[5];
    const float* kb   = (const float*)d_in[6];
    const float* vw   = (const float*)d_in[7];
    const float* vb   = (const float*)d_in[8];
    const float* w2   = (const float*)d_in[9];
    const float* b2   = (const float*)d_in[10];
    float* out = (float*)d_out;

    cudaFuncSetAttribute(qkv_mma,  cudaFuncAttributeMaxDynamicSharedMemorySize, Q_SMEM);
    cudaFuncSetAttribute(attn_mma, cudaFuncAttributeMaxDynamicSharedMemorySize, A_SMEM);

    setup_kernel<<<256, 256>>>(qw, kw, qb, vw);
    ln1_kernel<<<dim3(BKt, 2), 256>>>(x, ln1w, ln1b);
    qkv_mma<<<dim3(4, 2, BKt), 256, Q_SMEM>>>(vb);
    attn_mma<<<dim3(4, BKt), 256, A_SMEM>>>(x, out, w2, b2, ln1w, ln1b);
}

// round 16
// speedup vs baseline: 1.1746x; 1.0399x over previous
#include <cuda_runtime.h>
#include <cuda_bf16.h>
#include <math.h>
#include <stdint.h>

#define B_   4
#define N_   256
#define Kd   128
#define S_   256
#define BKt  512
#define BE   65536
#define SCALE 0.0625f

__device__ __align__(256) float          g_pe [S_ * N_];
__device__ __align__(256) float          g_peT[N_ * S_];
__device__ __align__(256) float          g_mu1[BKt * S_];
__device__ __align__(256) float          g_rs1[BKt * S_];
__device__ __align__(256) float          g_wkq[N_];
__device__ __align__(256) float          g_vcol[BKt * S_];
__device__ __align__(256) __nv_bfloat16  g_hb[BKt * BE];
__device__ __align__(256) __nv_bfloat16  g_Tb[BKt * BE];
__device__ __align__(256) __nv_bfloat16  g_Vt[BKt * BE];
__device__ __align__(256) __nv_bfloat16  g_wv[N_ * N_];
__device__ __align__(256) __nv_bfloat16  g_Mb[N_ * N_];

// ---------------- helpers ----------------
__device__ __forceinline__ uint32_t smem_u32(const void* p) {
    uint32_t a;
    asm("{ .reg .u64 t; cvta.to.shared.u64 t, %1; cvt.u32.u64 %0, t; }" : "=r"(a) : "l"(p));
    return a;
}
__device__ __forceinline__ void cpasync16(uint32_t dst, const void* src) {
    asm volatile("cp.async.cg.shared.global [%0], [%1], 16;" :: "r"(dst), "l"(src));
}
#define CP_COMMIT() asm volatile("cp.async.commit_group;" ::: "memory")
#define CP_WAIT0()  asm volatile("cp.async.wait_group 0;" ::: "memory")
#define CP_WAIT1()  asm volatile("cp.async.wait_group 1;" ::: "memory")

__device__ __forceinline__ void ldmat4(uint32_t& r0, uint32_t& r1, uint32_t& r2, uint32_t& r3, uint32_t addr) {
    asm volatile("ldmatrix.sync.aligned.m8n8.x4.shared.b16 {%0,%1,%2,%3}, [%4];"
                 : "=r"(r0), "=r"(r1), "=r"(r2), "=r"(r3) : "r"(addr));
}
__device__ __forceinline__ void mma16816(float* d, const uint32_t* a, const uint32_t* b) {
    asm volatile("mma.sync.aligned.m16n8k16.row.col.f32.bf16.bf16.f32 "
                 "{%0,%1,%2,%3},{%4,%5,%6,%7},{%8,%9},{%0,%1,%2,%3};"
                 : "+f"(d[0]), "+f"(d[1]), "+f"(d[2]), "+f"(d[3])
                 : "r"(a[0]), "r"(a[1]), "r"(a[2]), "r"(a[3]), "r"(b[0]), "r"(b[1]));
}
__device__ __forceinline__ void tile_cp(uint32_t dst, const __nv_bfloat16* __restrict__ src,
                                        int rows, int tid, int nthr) {
    int total = rows * 8;
    for (int u = tid; u < total; u += nthr) {
        int row = u >> 3, seg = u & 7;
        cpasync16(dst + row * 128 + (((uint32_t)(seg ^ (row & 7))) << 4), src + row * 256 + seg * 8);
    }
}
__device__ __forceinline__ uint32_t a_addr(uint32_t base, int m0, int ksg, int lane) {
    int row = m0 + (lane & 15);
    int seg = ksg + (lane >> 4);
    return base + row * 128 + (((uint32_t)(seg ^ (row & 7))) << 4);
}
__device__ __forceinline__ uint32_t b_addr(uint32_t base, int n0, int ksg, int lane) {
    int row = n0 + ((lane >> 4) << 3) + (lane & 7);
    int seg = ksg + ((lane >> 3) & 1);
    return base + row * 128 + (((uint32_t)(seg ^ (row & 7))) << 4);
}

// ---------------------------------------------------------------------------
__global__ void __launch_bounds__(256) setup_kernel(const float* __restrict__ qw,
                                                    const float* __restrict__ kw,
                                                    const float* __restrict__ qb,
                                                    const float* __restrict__ vw) {
    __shared__ float kcol[256];
    __shared__ float part[256];
    int m = blockIdx.x, n = threadIdx.x;

    float freq = __expf(-(float)(n & ~1) * (9.210340371976184f / 256.0f));
    float a = (float)m * freq;
    float v = (n & 1) ? cosf(a) : sinf(a);
    g_pe [m * N_ + n] = v;
    g_peT[n * S_ + m] = v;

    g_wv[m * 256 + n] = __float2bfloat16(vw[m * 256 + n]);

    kcol[n] = kw[n * 256 + m];
    part[n] = qb[n] * kcol[n];
    __syncthreads();
    if (n == 0) {
        float s = 0.f;
        for (int i = 0; i < 256; i++) s += part[i];
        g_wkq[m] = s;
    }
    float s = 0.f;
#pragma unroll 4
    for (int i = 0; i < 256; i++) s += kcol[i] * qw[i * 256 + n];
    g_Mb[m * 256 + n] = __float2bfloat16(s);
}

// LN1 stats + bf16 h + fused vcol. Grid (bk, 2).
__global__ void __launch_bounds__(256) ln1_kernel(const float* __restrict__ x,
                                                  const float* __restrict__ w1,
                                                  const float* __restrict__ b1) {
    __shared__ float ps1[8 * 128], ps2[8 * 128];
    __shared__ float muS[128], rsS[128];
    __shared__ float w1s[256], b1s[256], wkqs[256];
    __shared__ float vp[8 * 128];
    int bk = blockIdx.x, half = blockIdx.y;
    int b = bk >> 7, k = bk & 127;
    int tid = threadIdx.x;
    int s_base = half * 128;
    const float* xb = x + ((size_t)b * N_ * Kd + k) * S_ + s_base;
    int sq = tid & 31;
    int nr = tid >> 5;
    int s4 = sq * 4;

    {
        float a1 = 0.f, a2 = 0.f, b1a = 0.f, b2a = 0.f, c1 = 0.f, c2 = 0.f, d1 = 0.f, d2 = 0.f;
        const float* xp = xb + (size_t)(nr * 32) * (Kd * S_) + s4;
#pragma unroll 8
        for (int i = 0; i < 32; i++) {
            float4 v = *(const float4*)(xp + (size_t)i * (Kd * S_));
            a1 += v.x; a2 += v.x * v.x;
            b1a += v.y; b2a += v.y * v.y;
            c1 += v.z; c2 += v.z * v.z;
            d1 += v.w; d2 += v.w * v.w;
        }
        ps1[nr * 128 + s4 + 0] = a1;  ps2[nr * 128 + s4 + 0] = a2;
        ps1[nr * 128 + s4 + 1] = b1a; ps2[nr * 128 + s4 + 1] = b2a;
        ps1[nr * 128 + s4 + 2] = c1;  ps2[nr * 128 + s4 + 2] = c2;
        ps1[nr * 128 + s4 + 3] = d1;  ps2[nr * 128 + s4 + 3] = d2;
    }
    w1s[tid] = w1[tid];
    b1s[tid] = b1[tid];
    wkqs[tid] = g_wkq[tid];
    __syncthreads();
    if (tid < 128) {
        float s1 = 0.f, s2 = 0.f;
#pragma unroll
        for (int g = 0; g < 8; g++) { s1 += ps1[g * 128 + tid]; s2 += ps2[g * 128 + tid]; }
        float mu = s1 * (1.f / N_);
        float var = s2 * (1.f / N_) - mu * mu;
        float rs = rsqrtf(var + 1e-5f);
        muS[tid] = mu;
        rsS[tid] = rs;
        g_mu1[bk * S_ + s_base + tid] = mu;
        g_rs1[bk * S_ + s_base + tid] = rs;
    }
    __syncthreads();

    __nv_bfloat16* hb = g_hb + (size_t)bk * BE;
    float accv[4] = {0.f, 0.f, 0.f, 0.f};
    float mus[4], rss[4];
#pragma unroll
    for (int si = 0; si < 4; si++) { mus[si] = muS[s4 + si]; rss[si] = rsS[s4 + si]; }

#pragma unroll
    for (int oct = 0; oct < 4; oct++) {
        int n0 = nr * 32 + oct * 8;
        float4 xv[8];
#pragma unroll
        for (int i = 0; i < 8; i++)
            xv[i] = *(const float4*)(xb + (size_t)(n0 + i) * (Kd * S_) + s4);
        float w1v[8], b1v[8], wkv[8];
#pragma unroll
        for (int i = 0; i < 8; i++) { w1v[i] = w1s[n0 + i]; b1v[i] = b1s[n0 + i]; wkv[i] = wkqs[n0 + i]; }
#pragma unroll
        for (int si = 0; si < 4; si++) {
            int s_glob = s_base + s4 + si;
            const float4* pep = (const float4*)(g_pe + (size_t)s_glob * N_ + n0);
            float4 pe0 = pep[0], pe1 = pep[1];
            float pev[8] = {pe0.x, pe0.y, pe0.z, pe0.w, pe1.x, pe1.y, pe1.z, pe1.w};
            uint32_t pk[4];
#pragma unroll
            for (int p = 0; p < 4; p++) {
                float x0 = ((const float*)&xv[2 * p])[si];
                float x1 = ((const float*)&xv[2 * p + 1])[si];
                float hv0 = (x0 - mus[si]) * rss[si] * w1v[2 * p]     + b1v[2 * p]     + pev[2 * p];
                float hv1 = (x1 - mus[si]) * rss[si] * w1v[2 * p + 1] + b1v[2 * p + 1] + pev[2 * p + 1];
                accv[si] += hv0 * wkv[2 * p] + hv1 * wkv[2 * p + 1];
                __nv_bfloat162 t = __floats2bfloat162_rn(hv0, hv1);
                pk[p] = *(uint32_t*)&t;
            }
            *(uint4*)(hb + (size_t)s_glob * N_ + n0) = make_uint4(pk[0], pk[1], pk[2], pk[3]);
        }
    }
#pragma unroll
    for (int si = 0; si < 4; si++) vp[nr * 128 + s4 + si] = accv[si];
    __syncthreads();
    if (tid < 128) {
        float s = 0.f;
#pragma unroll
        for (int g = 0; g < 8; g++) s += vp[g * 128 + tid];
        g_vcol[bk * 256 + s_base + tid] = s;
    }
}

// ---------------- qkv_mma ----------------
#define Q_A0   0
#define Q_A1   16384
#define Q_B0   32768
#define Q_B1   49152
#define Q_BIAS 65536
#define Q_SMEM 66560

__global__ void __launch_bounds__(256, 2)
qkv_mma(const float* __restrict__ vb_) {
    extern __shared__ char smem_dyn[];
    uint32_t sb = smem_u32(smem_dyn);
    int tid = threadIdx.x, lane = tid & 31, wid = tid >> 5;
    int wm = wid >> 2, wn = wid & 3;
    int m_base = wm * 64, n_base = wn * 32;

    int mt = blockIdx.x >> 1, nt = blockIdx.x & 1;
    int which = blockIdx.y, bk = blockIdx.z;

    const __nv_bfloat16* hb = g_hb + (size_t)bk * BE;
    const __nv_bfloat16 *Ag, *Bg;
    __nv_bfloat16* outp;
    if (which == 0) { Ag = hb + mt * 128 * 256;     Bg = g_Mb + nt * 128 * 256; outp = g_Tb + (size_t)bk * BE; }
    else            { Ag = g_wv + mt * 128 * 256;   Bg = hb + nt * 128 * 256;   outp = g_Vt + (size_t)bk * BE; }

    float* biass = (float*)(smem_dyn + Q_BIAS);
    if (tid < 256) biass[tid] = vb_[tid];

    float acc[4][4][4] = {};

    tile_cp(sb + Q_A0, Ag, 128, tid, 256);
    tile_cp(sb + Q_B0, Bg, 128, tid, 256);
    CP_COMMIT();

    for (int c = 0; c < 4; c++) {
        int cur = c & 1;
        if (c + 1 < 4) {
            tile_cp(sb + (cur ? Q_A0 : Q_A1), Ag + (c + 1) * 64, 128, tid, 256);
            tile_cp(sb + (cur ? Q_B0 : Q_B1), Bg + (c + 1) * 64, 128, tid, 256);
            CP_COMMIT();
            CP_WAIT1();
        } else {
            CP_WAIT0();
        }
        __syncthreads();
        uint32_t aB = sb + (cur ? Q_A1 : Q_A0);
        uint32_t bB = sb + (cur ? Q_B1 : Q_B0);
#pragma unroll
        for (int kk = 0; kk < 4; kk++) {
            int ksg = kk * 2;
            uint32_t a[4][4];
#pragma unroll
            for (int mi = 0; mi < 4; mi++)
                ldmat4(a[mi][0], a[mi][1], a[mi][2], a[mi][3], a_addr(aB, m_base + mi * 16, ksg, lane));
            uint32_t bfr[4][2];
#pragma unroll
            for (int nj = 0; nj < 2; nj++) {
                uint32_t r0, r1, r2, r3;
                ldmat4(r0, r1, r2, r3, b_addr(bB, n_base + nj * 16, ksg, lane));
                bfr[nj * 2][0] = r0;     bfr[nj * 2][1] = r1;
                bfr[nj * 2 + 1][0] = r2; bfr[nj * 2 + 1][1] = r3;
            }
#pragma unroll
            for (int mi = 0; mi < 4; mi++)
#pragma unroll
                for (int ni = 0; ni < 4; ni++)
                    mma16816(acc[mi][ni], a[mi], bfr[ni]);
        }
        __syncthreads();
    }

#pragma unroll
    for (int mi = 0; mi < 4; mi++) {
#pragma unroll
        for (int h = 0; h < 2; h++) {
            int rloc = m_base + mi * 16 + h * 8 + (lane >> 2);
            int grow = mt * 128 + rloc;
            float rb = (which == 1) ? biass[grow] : 0.f;
#pragma unroll
            for (int ni = 0; ni < 4; ni++) {
                int cloc = n_base + ni * 8 + (lane & 3) * 2;
                int gcol = nt * 128 + cloc;
                float v0 = acc[mi][ni][h * 2 + 0] + rb;
                float v1 = acc[mi][ni][h * 2 + 1] + rb;
                __nv_bfloat162 t = __floats2bfloat162_rn(v0, v1);
                *(uint32_t*)(outp + grow * 256 + gcol) = *(uint32_t*)&t;
            }
        }
    }
}

// ---------------- attn_mma ----------------
#define A_QS   0
#define A_BS   32768
#define A_PS   65536
#define A_RED  98304
#define A_FROW 99328
#define A_MU1  99584
#define A_RS1  99840
#define A_MU2  100096
#define A_RS2  100352
#define A_W1   100608
#define A_B1   101632
#define A_W2   102656
#define A_B2   103680
#define A_VC   104704
#define A_SMEM 105728
// epilogue: Os[64][257] = 65792 B at offset 0; stats partials at 66048
#define A_SP1  66048
#define A_SP2  70144

__global__ void __launch_bounds__(256, 2)
attn_mma(const float* __restrict__ x, float* __restrict__ out,
         const float* __restrict__ w2, const float* __restrict__ b2,
         const float* __restrict__ w1, const float* __restrict__ b1) {
    extern __shared__ char smem_dyn[];
    uint32_t sb = smem_u32(smem_dyn);
    int tid = threadIdx.x, lane = tid & 31, wid = tid >> 5;
    int wm = wid >> 2, wn = wid & 3;
    int q0 = blockIdx.x * 64;
    int bk = blockIdx.y;

    float* sRed  = (float*)(smem_dyn + A_RED);
    float* frowS = (float*)(smem_dyn + A_FROW);
    float* mu1s  = (float*)(smem_dyn + A_MU1);
    float* rs1s  = (float*)(smem_dyn + A_RS1);
    float* mu2s  = (float*)(smem_dyn + A_MU2);
    float* rs2s  = (float*)(smem_dyn + A_RS2);
    float* w1s   = (float*)(smem_dyn + A_W1);
    float* b1s   = (float*)(smem_dyn + A_B1);
    float* w2s   = (float*)(smem_dyn + A_W2);
    float* b2s   = (float*)(smem_dyn + A_B2);
    float* vcS   = (float*)(smem_dyn + A_VC);
    if (tid < 256) {
        w1s[tid] = w1[tid]; b1s[tid] = b1[tid];
        w2s[tid] = w2[tid]; b2s[tid] = b2[tid];
        vcS[tid] = g_vcol[bk * 256 + tid];
    }
    if (tid < 64)  { mu1s[tid] = g_mu1[bk * S_ + q0 + tid]; rs1s[tid] = g_rs1[bk * S_ + q0 + tid]; }

    const __nv_bfloat16* Qg = g_Tb + (size_t)bk * BE + q0 * 256;
    const __nv_bfloat16* Kg = g_hb + (size_t)bk * BE;
    const __nv_bfloat16* Vg = g_Vt + (size_t)bk * BE;

    float acc[2][8][4] = {};

    // ---- phase 1: logits = T . h^T ----
    for (int jc = 0; jc < 4; jc++)
        tile_cp(sb + A_QS + jc * 8192, Qg + jc * 64, 64, tid, 256);
    tile_cp(sb + A_BS, Kg, 256, tid, 256);
    CP_COMMIT();
    for (int jc = 0; jc < 4; jc++) {
        if (jc < 3) {
            tile_cp(sb + ((jc & 1) ? A_BS : A_PS), Kg + (jc + 1) * 64, 256, tid, 256);
            CP_COMMIT(); CP_WAIT1();
        } else CP_WAIT0();
        __syncthreads();
        uint32_t aB = sb + A_QS + jc * 8192;
        uint32_t bB = sb + ((jc & 1) ? A_PS : A_BS);
#pragma unroll
        for (int kk = 0; kk < 4; kk++) {
            int ksg = kk * 2;
            uint32_t a[2][4];
#pragma unroll
            for (int mi = 0; mi < 2; mi++)
                ldmat4(a[mi][0], a[mi][1], a[mi][2], a[mi][3], a_addr(aB, wm * 32 + mi * 16, ksg, lane));
#pragma unroll
            for (int nj = 0; nj < 4; nj++) {
                uint32_t r0, r1, r2, r3;
                ldmat4(r0, r1, r2, r3, b_addr(bB, wn * 64 + nj * 16, ksg, lane));
                uint32_t b0[2] = {r0, r1}, b1v[2] = {r2, r3};
#pragma unroll
                for (int mi = 0; mi < 2; mi++) {
                    mma16816(acc[mi][nj * 2],     a[mi], b0);
                    mma16816(acc[mi][nj * 2 + 1], a[mi], b1v);
                }
            }
        }
        __syncthreads();
    }

    // add vcol[k]
#pragma unroll
    for (int mi = 0; mi < 2; mi++)
#pragma unroll
        for (int ni = 0; ni < 8; ni++) {
            int k0 = wn * 64 + ni * 8 + (lane & 3) * 2;
            float v0 = vcS[k0], v1 = vcS[k0 + 1];
            acc[mi][ni][0] += v0; acc[mi][ni][1] += v1;
            acc[mi][ni][2] += v0; acc[mi][ni][3] += v1;
        }

    // prefetch V chunk0
    tile_cp(sb + A_BS, Vg, 256, tid, 256);
    CP_COMMIT();

    // ---- softmax ----
#pragma unroll
    for (int mi = 0; mi < 2; mi++)
#pragma unroll
        for (int h = 0; h < 2; h++) {
            float pm = -1e30f;
#pragma unroll
            for (int ni = 0; ni < 8; ni++) {
                pm = fmaxf(pm, acc[mi][ni][h * 2 + 0]);
                pm = fmaxf(pm, acc[mi][ni][h * 2 + 1]);
            }
            pm = fmaxf(pm, __shfl_xor_sync(0xffffffffu, pm, 1));
            pm = fmaxf(pm, __shfl_xor_sync(0xffffffffu, pm, 2));
            if ((lane & 3) == 0)
                sRed[wn * 64 + wm * 32 + mi * 16 + h * 8 + (lane >> 2)] = pm;
        }
    __syncthreads();
    float rm[2][2];
#pragma unroll
    for (int mi = 0; mi < 2; mi++)
#pragma unroll
        for (int h = 0; h < 2; h++) {
            int r = wm * 32 + mi * 16 + h * 8 + (lane >> 2);
            rm[mi][h] = fmaxf(fmaxf(sRed[r], sRed[64 + r]), fmaxf(sRed[128 + r], sRed[192 + r]));
        }
    __syncthreads();
#pragma unroll
    for (int mi = 0; mi < 2; mi++)
#pragma unroll
        for (int h = 0; h < 2; h++) {
            int r = wm * 32 + mi * 16 + h * 8 + (lane >> 2);
            float ps = 0.f;
#pragma unroll
            for (int ni = 0; ni < 8; ni++) {
                float e0 = __expf(acc[mi][ni][h * 2 + 0] - rm[mi][h]);
                float e1 = __expf(acc[mi][ni][h * 2 + 1] - rm[mi][h]);
                ps += e0 + e1;
                __nv_bfloat162 t = __floats2bfloat162_rn(e0, e1);
                int cl = (wn * 64 + ni * 8 + (lane & 3) * 2) & 63;
                int cb = cl * 2;
                uint32_t addr = sb + A_PS + wn * 8192 + r * 128
                              + ((((uint32_t)cb >> 4) ^ (uint32_t)(r & 7)) << 4) + (cb & 15);
                asm volatile("st.shared.b32 [%0], %1;" :: "r"(addr), "r"(*(uint32_t*)&t));
            }
            ps += __shfl_xor_sync(0xffffffffu, ps, 1);
            ps += __shfl_xor_sync(0xffffffffu, ps, 2);
            if ((lane & 3) == 0) sRed[wn * 64 + r] = ps;
        }
    __syncthreads();
    if (tid < 64)
        frowS[tid] = SCALE / (sRed[tid] + sRed[64 + tid] + sRed[128 + tid] + sRed[192 + tid]);
#pragma unroll
    for (int mi = 0; mi < 2; mi++)
#pragma unroll
        for (int ni = 0; ni < 8; ni++)
#pragma unroll
            for (int j = 0; j < 4; j++) acc[mi][ni][j] = 0.f;
    __syncthreads();

    // ---- phase 2: O = expP . Vt^T ----
    for (int sc = 0; sc < 4; sc++) {
        if (sc < 3) {
            tile_cp(sb + ((sc & 1) ? A_BS : A_QS), Vg + (sc + 1) * 64, 256, tid, 256);
            CP_COMMIT(); CP_WAIT1();
        } else CP_WAIT0();
        __syncthreads();
        uint32_t aB = sb + A_PS + sc * 8192;
        uint32_t bB = sb + ((sc & 1) ? A_QS : A_BS);
#pragma unroll
        for (int kk = 0; kk < 4; kk++) {
            int ksg = kk * 2;
            uint32_t a[2][4];
#pragma unroll
            for (int mi = 0; mi < 2; mi++)
                ldmat4(a[mi][0], a[mi][1], a[mi][2], a[mi][3], a_addr(aB, wm * 32 + mi * 16, ksg, lane));
#pragma unroll
            for (int nj = 0; nj < 4; nj++) {
                uint32_t r0, r1, r2, r3;
                ldmat4(r0, r1, r2, r3, b_addr(bB, wn * 64 + nj * 16, ksg, lane));
                uint32_t b0[2] = {r0, r1}, b1v[2] = {r2, r3};
#pragma unroll
                for (int mi = 0; mi < 2; mi++) {
                    mma16816(acc[mi][nj * 2],     a[mi], b0);
                    mma16816(acc[mi][nj * 2 + 1], a[mi], b1v);
                }
            }
        }
        __syncthreads();
    }

    // ---- epilogue ----
    float* Os  = (float*)smem_dyn;                 // [64][257]
    float* sp1 = (float*)(smem_dyn + A_SP1);       // [16][64]
    float* sp2 = (float*)(smem_dyn + A_SP2);       // [16][64]
#pragma unroll
    for (int mi = 0; mi < 2; mi++)
#pragma unroll
        for (int h = 0; h < 2; h++) {
            int r = wm * 32 + mi * 16 + h * 8 + (lane >> 2);
            float fr = frowS[r];
#pragma unroll
            for (int ni = 0; ni < 8; ni++) {
                int d = wn * 64 + ni * 8 + (lane & 3) * 2;
                Os[r * 257 + d]     = acc[mi][ni][h * 2 + 0] * fr;
                Os[r * 257 + d + 1] = acc[mi][ni][h * 2 + 1] * fr;
            }
        }
    __syncthreads();

    int b = bk >> 7, kk2 = bk & 127;
    const float* xb = x   + (size_t)b * (N_ * Kd * S_) + kk2 * S_ + q0;
    float*       ob = out + (size_t)b * (N_ * Kd * S_) + kk2 * S_ + q0;

    // loop1: Os += h recomputed (float4 over qi), with fused LN2 partial stats
    {
        int qb4 = (tid & 15) * 4;
        int d0  = tid >> 4;
        float s1[4] = {0.f, 0.f, 0.f, 0.f};
        float s2[4] = {0.f, 0.f, 0.f, 0.f};
#pragma unroll
        for (int it = 0; it < 16; it++) {
            int d = it * 16 + d0;
            float4 xv = *(const float4*)(xb + (size_t)d * (Kd * S_) + qb4);
            float4 pe = *(const float4*)(g_peT + (size_t)d * S_ + q0 + qb4);
            float w1v = w1s[d], b1v = b1s[d];
            float v0 = Os[(qb4 + 0) * 257 + d] + (xv.x - mu1s[qb4 + 0]) * rs1s[qb4 + 0] * w1v + b1v + pe.x;
            float v1 = Os[(qb4 + 1) * 257 + d] + (xv.y - mu1s[qb4 + 1]) * rs1s[qb4 + 1] * w1v + b1v + pe.y;
            float v2 = Os[(qb4 + 2) * 257 + d] + (xv.z - mu1s[qb4 + 2]) * rs1s[qb4 + 2] * w1v + b1v + pe.z;
            float v3 = Os[(qb4 + 3) * 257 + d] + (xv.w - mu1s[qb4 + 3]) * rs1s[qb4 + 3] * w1v + b1v + pe.w;
            Os[(qb4 + 0) * 257 + d] = v0;
            Os[(qb4 + 1) * 257 + d] = v1;
            Os[(qb4 + 2) * 257 + d] = v2;
            Os[(qb4 + 3) * 257 + d] = v3;
            s1[0] += v0; s2[0] += v0 * v0;
            s1[1] += v1; s2[1] += v1 * v1;
            s1[2] += v2; s2[2] += v2 * v2;
            s1[3] += v3; s2[3] += v3 * v3;
        }
#pragma unroll
        for (int i = 0; i < 4; i++) {
            sp1[d0 * 64 + qb4 + i] = s1[i];
            sp2[d0 * 64 + qb4 + i] = s2[i];
        }
    }
    __syncthreads();

    if (tid < 64) {
        float s1 = 0.f, s2 = 0.f;
#pragma unroll
        for (int g = 0; g < 16; g++) { s1 += sp1[g * 64 + tid]; s2 += sp2[g * 64 + tid]; }
        float mu = s1 * (1.f / N_);
        float var = s2 * (1.f / N_) - mu * mu;
        mu2s[tid] = mu;
        rs2s[tid] = rsqrtf(var + 1e-5f);
    }
    __syncthreads();

    // loop3: normalize + x + store (float4 over qi)
    {
        int qb4 = (tid & 15) * 4;
        int d0  = tid >> 4;
#pragma unroll
        for (int it = 0; it < 16; it++) {
            int d = it * 16 + d0;
            float4 xv = *(const float4*)(xb + (size_t)d * (Kd * S_) + qb4);
            float w2v = w2s[d], b2v = b2s[d];
            float4 o;
            o.x = (Os[(qb4 + 0) * 257 + d] - mu2s[qb4 + 0]) * rs2s[qb4 + 0] * w2v + b2v + xv.x;
            o.y = (Os[(qb4 + 1) * 257 + d] - mu2s[qb4 + 1]) * rs2s[qb4 + 1] * w2v + b2v + xv.y;
            o.z = (Os[(qb4 + 2) * 257 + d] - mu2s[qb4 + 2]) * rs2s[qb4 + 2] * w2v + b2v + xv.z;
            o.w = (Os[(qb4 + 3) * 257 + d] - mu2s[qb4 + 3]) * rs2s[qb4 + 3] * w2v + b2v + xv.w;
            *(float4*)(ob + (size_t)d * (Kd * S_) + qb4) = o;
        }
    }
}

extern "C" void kernel_launch(void* const* d_in, const int* in_sizes, int n_in,
                              void* d_out, int out_size) {
    const float* x    = (const float*)d_in[0];
    const float* ln1w = (const float*)d_in[1];
    const float* ln1b = (const float*)d_in[2];
    const float* qw   = (const float*)d_in[3];
    const float* qb   = (const float*)d_in[4];
    const float* kw   = (const float*)d_in[5];
    const float* kb   = (const float*)d_in[6];
    const float* vw   = (const float*)d_in[7];
    const float* vb   = (const float*)d_in[8];
    const float* w2   = (const float*)d_in[9];
    const float* b2   = (const float*)d_in[10];
    float* out = (float*)d_out;

    cudaFuncSetAttribute(qkv_mma,  cudaFuncAttributeMaxDynamicSharedMemorySize, Q_SMEM);
    cudaFuncSetAttribute(attn_mma, cudaFuncAttributeMaxDynamicSharedMemorySize, A_SMEM);

    setup_kernel<<<256, 256>>>(qw, kw, qb, vw);
    ln1_kernel<<<dim3(BKt, 2), 256>>>(x, ln1w, ln1b);
    qkv_mma<<<dim3(4, 2, BKt), 256, Q_SMEM>>>(vb);
    attn_mma<<<dim3(4, BKt), 256, A_SMEM>>>(x, out, w2, b2, ln1w, ln1b);
}

// round 17
// speedup vs baseline: 1.2060x; 1.0267x over previous
#include <cuda_runtime.h>
#include <cuda_bf16.h>
#include <math.h>
#include <stdint.h>

#define B_   4
#define N_   256
#define Kd   128
#define S_   256
#define BKt  512
#define BE   65536
#define SCALE 0.0625f

__device__ __align__(256) float          g_pe [S_ * N_];
__device__ __align__(256) float          g_peT[N_ * S_];
__device__ __align__(256) float          g_mu1[BKt * S_];
__device__ __align__(256) float          g_rs1[BKt * S_];
__device__ __align__(256) float          g_wkq[N_];
__device__ __align__(256) float          g_vcol[BKt * S_];
__device__ __align__(256) __nv_bfloat16  g_hb[BKt * BE];
__device__ __align__(256) __nv_bfloat16  g_Vt[BKt * BE];
__device__ __align__(256) __nv_bfloat16  g_wv[N_ * N_];
__device__ __align__(256) __nv_bfloat16  g_Mb[N_ * N_];

// ---------------- helpers ----------------
__device__ __forceinline__ uint32_t smem_u32(const void* p) {
    uint32_t a;
    asm("{ .reg .u64 t; cvta.to.shared.u64 t, %1; cvt.u32.u64 %0, t; }" : "=r"(a) : "l"(p));
    return a;
}
__device__ __forceinline__ void cpasync16(uint32_t dst, const void* src) {
    asm volatile("cp.async.cg.shared.global [%0], [%1], 16;" :: "r"(dst), "l"(src));
}
#define CP_COMMIT() asm volatile("cp.async.commit_group;" ::: "memory")
#define CP_WAIT0()  asm volatile("cp.async.wait_group 0;" ::: "memory")
#define CP_WAIT1()  asm volatile("cp.async.wait_group 1;" ::: "memory")

__device__ __forceinline__ void ldmat4(uint32_t& r0, uint32_t& r1, uint32_t& r2, uint32_t& r3, uint32_t addr) {
    asm volatile("ldmatrix.sync.aligned.m8n8.x4.shared.b16 {%0,%1,%2,%3}, [%4];"
                 : "=r"(r0), "=r"(r1), "=r"(r2), "=r"(r3) : "r"(addr));
}
__device__ __forceinline__ void mma16816(float* d, const uint32_t* a, const uint32_t* b) {
    asm volatile("mma.sync.aligned.m16n8k16.row.col.f32.bf16.bf16.f32 "
                 "{%0,%1,%2,%3},{%4,%5,%6,%7},{%8,%9},{%0,%1,%2,%3};"
                 : "+f"(d[0]), "+f"(d[1]), "+f"(d[2]), "+f"(d[3])
                 : "r"(a[0]), "r"(a[1]), "r"(a[2]), "r"(a[3]), "r"(b[0]), "r"(b[1]));
}
__device__ __forceinline__ void tile_cp(uint32_t dst, const __nv_bfloat16* __restrict__ src,
                                        int rows, int tid, int nthr) {
    int total = rows * 8;
    for (int u = tid; u < total; u += nthr) {
        int row = u >> 3, seg = u & 7;
        cpasync16(dst + row * 128 + (((uint32_t)(seg ^ (row & 7))) << 4), src + row * 256 + seg * 8);
    }
}
__device__ __forceinline__ uint32_t a_addr(uint32_t base, int m0, int ksg, int lane) {
    int row = m0 + (lane & 15);
    int seg = ksg + (lane >> 4);
    return base + row * 128 + (((uint32_t)(seg ^ (row & 7))) << 4);
}
__device__ __forceinline__ uint32_t b_addr(uint32_t base, int n0, int ksg, int lane) {
    int row = n0 + ((lane >> 4) << 3) + (lane & 7);
    int seg = ksg + ((lane >> 3) & 1);
    return base + row * 128 + (((uint32_t)(seg ^ (row & 7))) << 4);
}

// ---------------------------------------------------------------------------
__global__ void __launch_bounds__(256) setup_kernel(const float* __restrict__ qw,
                                                    const float* __restrict__ kw,
                                                    const float* __restrict__ qb,
                                                    const float* __restrict__ vw) {
    __shared__ float kcol[256];
    __shared__ float part[256];
    int m = blockIdx.x, n = threadIdx.x;

    float freq = __expf(-(float)(n & ~1) * (9.210340371976184f / 256.0f));
    float a = (float)m * freq;
    float v = (n & 1) ? cosf(a) : sinf(a);
    g_pe [m * N_ + n] = v;
    g_peT[n * S_ + m] = v;

    g_wv[m * 256 + n] = __float2bfloat16(vw[m * 256 + n]);

    kcol[n] = kw[n * 256 + m];
    part[n] = qb[n] * kcol[n];
    __syncthreads();
    if (n == 0) {
        float s = 0.f;
        for (int i = 0; i < 256; i++) s += part[i];
        g_wkq[m] = s;
    }
    float s = 0.f;
#pragma unroll 4
    for (int i = 0; i < 256; i++) s += kcol[i] * qw[i * 256 + n];
    g_Mb[m * 256 + n] = __float2bfloat16(s);
}

// LN1 stats + bf16 h + fused vcol. Grid (bk, 2).
__global__ void __launch_bounds__(256) ln1_kernel(const float* __restrict__ x,
                                                  const float* __restrict__ w1,
                                                  const float* __restrict__ b1) {
    __shared__ float ps1[8 * 128], ps2[8 * 128];
    __shared__ float muS[128], rsS[128];
    __shared__ float w1s[256], b1s[256], wkqs[256];
    __shared__ float vp[8 * 128];
    int bk = blockIdx.x, half = blockIdx.y;
    int b = bk >> 7, k = bk & 127;
    int tid = threadIdx.x;
    int s_base = half * 128;
    const float* xb = x + ((size_t)b * N_ * Kd + k) * S_ + s_base;
    int sq = tid & 31;
    int nr = tid >> 5;
    int s4 = sq * 4;

    {
        float a1 = 0.f, a2 = 0.f, b1a = 0.f, b2a = 0.f, c1 = 0.f, c2 = 0.f, d1 = 0.f, d2 = 0.f;
        const float* xp = xb + (size_t)(nr * 32) * (Kd * S_) + s4;
#pragma unroll 8
        for (int i = 0; i < 32; i++) {
            float4 v = *(const float4*)(xp + (size_t)i * (Kd * S_));
            a1 += v.x; a2 += v.x * v.x;
            b1a += v.y; b2a += v.y * v.y;
            c1 += v.z; c2 += v.z * v.z;
            d1 += v.w; d2 += v.w * v.w;
        }
        ps1[nr * 128 + s4 + 0] = a1;  ps2[nr * 128 + s4 + 0] = a2;
        ps1[nr * 128 + s4 + 1] = b1a; ps2[nr * 128 + s4 + 1] = b2a;
        ps1[nr * 128 + s4 + 2] = c1;  ps2[nr * 128 + s4 + 2] = c2;
        ps1[nr * 128 + s4 + 3] = d1;  ps2[nr * 128 + s4 + 3] = d2;
    }
    w1s[tid] = w1[tid];
    b1s[tid] = b1[tid];
    wkqs[tid] = g_wkq[tid];
    __syncthreads();
    if (tid < 128) {
        float s1 = 0.f, s2 = 0.f;
#pragma unroll
        for (int g = 0; g < 8; g++) { s1 += ps1[g * 128 + tid]; s2 += ps2[g * 128 + tid]; }
        float mu = s1 * (1.f / N_);
        float var = s2 * (1.f / N_) - mu * mu;
        float rs = rsqrtf(var + 1e-5f);
        muS[tid] = mu;
        rsS[tid] = rs;
        g_mu1[bk * S_ + s_base + tid] = mu;
        g_rs1[bk * S_ + s_base + tid] = rs;
    }
    __syncthreads();

    __nv_bfloat16* hb = g_hb + (size_t)bk * BE;
    float accv[4] = {0.f, 0.f, 0.f, 0.f};
    float mus[4], rss[4];
#pragma unroll
    for (int si = 0; si < 4; si++) { mus[si] = muS[s4 + si]; rss[si] = rsS[s4 + si]; }

#pragma unroll
    for (int oct = 0; oct < 4; oct++) {
        int n0 = nr * 32 + oct * 8;
        float4 xv[8];
#pragma unroll
        for (int i = 0; i < 8; i++)
            xv[i] = *(const float4*)(xb + (size_t)(n0 + i) * (Kd * S_) + s4);
        float w1v[8], b1v[8], wkv[8];
#pragma unroll
        for (int i = 0; i < 8; i++) { w1v[i] = w1s[n0 + i]; b1v[i] = b1s[n0 + i]; wkv[i] = wkqs[n0 + i]; }
#pragma unroll
        for (int si = 0; si < 4; si++) {
            int s_glob = s_base + s4 + si;
            const float4* pep = (const float4*)(g_pe + (size_t)s_glob * N_ + n0);
            float4 pe0 = pep[0], pe1 = pep[1];
            float pev[8] = {pe0.x, pe0.y, pe0.z, pe0.w, pe1.x, pe1.y, pe1.z, pe1.w};
            uint32_t pk[4];
#pragma unroll
            for (int p = 0; p < 4; p++) {
                float x0 = ((const float*)&xv[2 * p])[si];
                float x1 = ((const float*)&xv[2 * p + 1])[si];
                float hv0 = (x0 - mus[si]) * rss[si] * w1v[2 * p]     + b1v[2 * p]     + pev[2 * p];
                float hv1 = (x1 - mus[si]) * rss[si] * w1v[2 * p + 1] + b1v[2 * p + 1] + pev[2 * p + 1];
                accv[si] += hv0 * wkv[2 * p] + hv1 * wkv[2 * p + 1];
                __nv_bfloat162 t = __floats2bfloat162_rn(hv0, hv1);
                pk[p] = *(uint32_t*)&t;
            }
            *(uint4*)(hb + (size_t)s_glob * N_ + n0) = make_uint4(pk[0], pk[1], pk[2], pk[3]);
        }
    }
#pragma unroll
    for (int si = 0; si < 4; si++) vp[nr * 128 + s4 + si] = accv[si];
    __syncthreads();
    if (tid < 128) {
        float s = 0.f;
#pragma unroll
        for (int g = 0; g < 8; g++) s += vp[g * 128 + tid];
        g_vcol[bk * 256 + s_base + tid] = s;
    }
}

// ---------------- v_mma: Vt = Wv . h^T only ----------------
#define Q_A0   0
#define Q_A1   16384
#define Q_B0   32768
#define Q_B1   49152
#define Q_BIAS 65536
#define Q_SMEM 66560

__global__ void __launch_bounds__(256, 2)
v_mma(const float* __restrict__ vb_) {
    extern __shared__ char smem_dyn[];
    uint32_t sb = smem_u32(smem_dyn);
    int tid = threadIdx.x, lane = tid & 31, wid = tid >> 5;
    int wm = wid >> 2, wn = wid & 3;
    int m_base = wm * 64, n_base = wn * 32;

    int mt = blockIdx.x >> 1, nt = blockIdx.x & 1;
    int bk = blockIdx.y;

    const __nv_bfloat16* hb = g_hb + (size_t)bk * BE;
    const __nv_bfloat16* Ag = g_wv + mt * 128 * 256;
    const __nv_bfloat16* Bg = hb + nt * 128 * 256;
    __nv_bfloat16* outp = g_Vt + (size_t)bk * BE;

    float* biass = (float*)(smem_dyn + Q_BIAS);
    if (tid < 256) biass[tid] = vb_[tid];

    float acc[4][4][4] = {};

    tile_cp(sb + Q_A0, Ag, 128, tid, 256);
    tile_cp(sb + Q_B0, Bg, 128, tid, 256);
    CP_COMMIT();

    for (int c = 0; c < 4; c++) {
        int cur = c & 1;
        if (c + 1 < 4) {
            tile_cp(sb + (cur ? Q_A0 : Q_A1), Ag + (c + 1) * 64, 128, tid, 256);
            tile_cp(sb + (cur ? Q_B0 : Q_B1), Bg + (c + 1) * 64, 128, tid, 256);
            CP_COMMIT();
            CP_WAIT1();
        } else {
            CP_WAIT0();
        }
        __syncthreads();
        uint32_t aB = sb + (cur ? Q_A1 : Q_A0);
        uint32_t bB = sb + (cur ? Q_B1 : Q_B0);
#pragma unroll
        for (int kk = 0; kk < 4; kk++) {
            int ksg = kk * 2;
            uint32_t a[4][4];
#pragma unroll
            for (int mi = 0; mi < 4; mi++)
                ldmat4(a[mi][0], a[mi][1], a[mi][2], a[mi][3], a_addr(aB, m_base + mi * 16, ksg, lane));
            uint32_t bfr[4][2];
#pragma unroll
            for (int nj = 0; nj < 2; nj++) {
                uint32_t r0, r1, r2, r3;
                ldmat4(r0, r1, r2, r3, b_addr(bB, n_base + nj * 16, ksg, lane));
                bfr[nj * 2][0] = r0;     bfr[nj * 2][1] = r1;
                bfr[nj * 2 + 1][0] = r2; bfr[nj * 2 + 1][1] = r3;
            }
#pragma unroll
            for (int mi = 0; mi < 4; mi++)
#pragma unroll
                for (int ni = 0; ni < 4; ni++)
                    mma16816(acc[mi][ni], a[mi], bfr[ni]);
        }
        __syncthreads();
    }

#pragma unroll
    for (int mi = 0; mi < 4; mi++) {
#pragma unroll
        for (int h = 0; h < 2; h++) {
            int rloc = m_base + mi * 16 + h * 8 + (lane >> 2);
            int grow = mt * 128 + rloc;
            float rb = biass[grow];
#pragma unroll
            for (int ni = 0; ni < 4; ni++) {
                int gcol = nt * 128 + n_base + ni * 8 + (lane & 3) * 2;
                __nv_bfloat162 t = __floats2bfloat162_rn(acc[mi][ni][h * 2 + 0] + rb,
                                                         acc[mi][ni][h * 2 + 1] + rb);
                *(uint32_t*)(outp + grow * 256 + gcol) = *(uint32_t*)&t;
            }
        }
    }
}

// ---------------- attn_mma: T-proj + logits + softmax + O, fused ------------
#define A_HQ   0        // h q-rows (phase A A-op) -> later P
#define A_BS   32768    // streaming buffer (even chunks)
#define A_TT   65536    // Mb odd chunks -> T tile -> V odd chunks
#define A_RED  98304
#define A_FROW 99328
#define A_MU1  99584
#define A_RS1  99840
#define A_MU2  100096
#define A_RS2  100352
#define A_W1   100608
#define A_B1   101632
#define A_W2   102656
#define A_B2   103680
#define A_VC   104704
#define A_SMEM 105728
#define A_SP1  66048
#define A_SP2  70144

__global__ void __launch_bounds__(256, 2)
attn_mma(const float* __restrict__ x, float* __restrict__ out,
         const float* __restrict__ w2, const float* __restrict__ b2,
         const float* __restrict__ w1, const float* __restrict__ b1) {
    extern __shared__ char smem_dyn[];
    uint32_t sb = smem_u32(smem_dyn);
    int tid = threadIdx.x, lane = tid & 31, wid = tid >> 5;
    int wm = wid >> 2, wn = wid & 3;
    int q0 = blockIdx.x * 64;
    int bk = blockIdx.y;

    float* sRed  = (float*)(smem_dyn + A_RED);
    float* frowS = (float*)(smem_dyn + A_FROW);
    float* mu1s  = (float*)(smem_dyn + A_MU1);
    float* rs1s  = (float*)(smem_dyn + A_RS1);
    float* mu2s  = (float*)(smem_dyn + A_MU2);
    float* rs2s  = (float*)(smem_dyn + A_RS2);
    float* w1s   = (float*)(smem_dyn + A_W1);
    float* b1s   = (float*)(smem_dyn + A_B1);
    float* w2s   = (float*)(smem_dyn + A_W2);
    float* b2s   = (float*)(smem_dyn + A_B2);
    float* vcS   = (float*)(smem_dyn + A_VC);
    if (tid < 256) {
        w1s[tid] = w1[tid]; b1s[tid] = b1[tid];
        w2s[tid] = w2[tid]; b2s[tid] = b2[tid];
        vcS[tid] = g_vcol[bk * 256 + tid];
    }
    if (tid < 64)  { mu1s[tid] = g_mu1[bk * S_ + q0 + tid]; rs1s[tid] = g_rs1[bk * S_ + q0 + tid]; }

    const __nv_bfloat16* Hq = g_hb + (size_t)bk * BE + q0 * 256;  // h q-rows
    const __nv_bfloat16* Kg = g_hb + (size_t)bk * BE;             // full h (keys)
    const __nv_bfloat16* Vg = g_Vt + (size_t)bk * BE;

    float acc[2][8][4] = {};

    // ======== phase A: T[64 x 256] = hq . M  (B = Mb rows = output cols) ====
    for (int jc = 0; jc < 4; jc++)
        tile_cp(sb + A_HQ + jc * 8192, Hq + jc * 64, 64, tid, 256);
    tile_cp(sb + A_BS, g_Mb, 256, tid, 256);
    CP_COMMIT();
    for (int c = 0; c < 4; c++) {
        if (c < 3) {
            tile_cp(sb + ((c & 1) ? A_BS : A_TT), g_Mb + (c + 1) * 64, 256, tid, 256);
            CP_COMMIT(); CP_WAIT1();
        } else CP_WAIT0();
        __syncthreads();
        uint32_t aB = sb + A_HQ + c * 8192;
        uint32_t bB = sb + ((c & 1) ? A_TT : A_BS);
#pragma unroll
        for (int kk = 0; kk < 4; kk++) {
            int ksg = kk * 2;
            uint32_t a[2][4];
#pragma unroll
            for (int mi = 0; mi < 2; mi++)
                ldmat4(a[mi][0], a[mi][1], a[mi][2], a[mi][3], a_addr(aB, wm * 32 + mi * 16, ksg, lane));
#pragma unroll
            for (int nj = 0; nj < 4; nj++) {
                uint32_t r0, r1, r2, r3;
                ldmat4(r0, r1, r2, r3, b_addr(bB, wn * 64 + nj * 16, ksg, lane));
                uint32_t b0[2] = {r0, r1}, b1v[2] = {r2, r3};
#pragma unroll
                for (int mi = 0; mi < 2; mi++) {
                    mma16816(acc[mi][nj * 2],     a[mi], b0);
                    mma16816(acc[mi][nj * 2 + 1], a[mi], b1v);
                }
            }
        }
        __syncthreads();
    }

    // T -> bf16 swizzled into TT (chunk = wn); prefetch h chunk0 -> BS
    tile_cp(sb + A_BS, Kg, 256, tid, 256);
    CP_COMMIT();
#pragma unroll
    for (int mi = 0; mi < 2; mi++)
#pragma unroll
        for (int h = 0; h < 2; h++) {
            int r = wm * 32 + mi * 16 + h * 8 + (lane >> 2);
#pragma unroll
            for (int ni = 0; ni < 8; ni++) {
                __nv_bfloat162 t = __floats2bfloat162_rn(acc[mi][ni][h * 2 + 0], acc[mi][ni][h * 2 + 1]);
                int cb = (ni * 8 + (lane & 3) * 2) * 2;
                uint32_t addr = sb + A_TT + wn * 8192 + r * 128
                              + ((((uint32_t)cb >> 4) ^ (uint32_t)(r & 7)) << 4) + (cb & 15);
                asm volatile("st.shared.b32 [%0], %1;" :: "r"(addr), "r"(*(uint32_t*)&t));
            }
        }
#pragma unroll
    for (int mi = 0; mi < 2; mi++)
#pragma unroll
        for (int ni = 0; ni < 8; ni++)
#pragma unroll
            for (int j = 0; j < 4; j++) acc[mi][ni][j] = 0.f;

    // ======== phase B: logits = T . h^T (A = TT, B streams BS<->HQ) =========
    for (int jc = 0; jc < 4; jc++) {
        if (jc < 3) {
            tile_cp(sb + ((jc & 1) ? A_BS : A_HQ), Kg + (jc + 1) * 64, 256, tid, 256);
            CP_COMMIT(); CP_WAIT1();
        } else CP_WAIT0();
        __syncthreads();
        uint32_t aB = sb + A_TT + jc * 8192;
        uint32_t bB = sb + ((jc & 1) ? A_HQ : A_BS);
#pragma unroll
        for (int kk = 0; kk < 4; kk++) {
            int ksg = kk * 2;
            uint32_t a[2][4];
#pragma unroll
            for (int mi = 0; mi < 2; mi++)
                ldmat4(a[mi][0], a[mi][1], a[mi][2], a[mi][3], a_addr(aB, wm * 32 + mi * 16, ksg, lane));
#pragma unroll
            for (int nj = 0; nj < 4; nj++) {
                uint32_t r0, r1, r2, r3;
                ldmat4(r0, r1, r2, r3, b_addr(bB, wn * 64 + nj * 16, ksg, lane));
                uint32_t b0[2] = {r0, r1}, b1v[2] = {r2, r3};
#pragma unroll
                for (int mi = 0; mi < 2; mi++) {
                    mma16816(acc[mi][nj * 2],     a[mi], b0);
                    mma16816(acc[mi][nj * 2 + 1], a[mi], b1v);
                }
            }
        }
        __syncthreads();
    }

    // add vcol[k]
#pragma unroll
    for (int mi = 0; mi < 2; mi++)
#pragma unroll
        for (int ni = 0; ni < 8; ni++) {
            int k0 = wn * 64 + ni * 8 + (lane & 3) * 2;
            float v0 = vcS[k0], v1 = vcS[k0 + 1];
            acc[mi][ni][0] += v0; acc[mi][ni][1] += v1;
            acc[mi][ni][2] += v0; acc[mi][ni][3] += v1;
        }

    // prefetch V chunk0 -> BS
    tile_cp(sb + A_BS, Vg, 256, tid, 256);
    CP_COMMIT();

    // ---- softmax (P -> HQ region, chunk = wn) ----
#pragma unroll
    for (int mi = 0; mi < 2; mi++)
#pragma unroll
        for (int h = 0; h < 2; h++) {
            float pm = -1e30f;
#pragma unroll
            for (int ni = 0; ni < 8; ni++) {
                pm = fmaxf(pm, acc[mi][ni][h * 2 + 0]);
                pm = fmaxf(pm, acc[mi][ni][h * 2 + 1]);
            }
            pm = fmaxf(pm, __shfl_xor_sync(0xffffffffu, pm, 1));
            pm = fmaxf(pm, __shfl_xor_sync(0xffffffffu, pm, 2));
            if ((lane & 3) == 0)
                sRed[wn * 64 + wm * 32 + mi * 16 + h * 8 + (lane >> 2)] = pm;
        }
    __syncthreads();
    float rm[2][2];
#pragma unroll
    for (int mi = 0; mi < 2; mi++)
#pragma unroll
        for (int h = 0; h < 2; h++) {
            int r = wm * 32 + mi * 16 + h * 8 + (lane >> 2);
            rm[mi][h] = fmaxf(fmaxf(sRed[r], sRed[64 + r]), fmaxf(sRed[128 + r], sRed[192 + r]));
        }
    __syncthreads();
#pragma unroll
    for (int mi = 0; mi < 2; mi++)
#pragma unroll
        for (int h = 0; h < 2; h++) {
            int r = wm * 32 + mi * 16 + h * 8 + (lane >> 2);
            float ps = 0.f;
#pragma unroll
            for (int ni = 0; ni < 8; ni++) {
                float e0 = __expf(acc[mi][ni][h * 2 + 0] - rm[mi][h]);
                float e1 = __expf(acc[mi][ni][h * 2 + 1] - rm[mi][h]);
                ps += e0 + e1;
                __nv_bfloat162 t = __floats2bfloat162_rn(e0, e1);
                int cb = ((ni * 8 + (lane & 3) * 2) & 63) * 2;
                uint32_t addr = sb + A_HQ + wn * 8192 + r * 128
                              + ((((uint32_t)cb >> 4) ^ (uint32_t)(r & 7)) << 4) + (cb & 15);
                asm volatile("st.shared.b32 [%0], %1;" :: "r"(addr), "r"(*(uint32_t*)&t));
            }
            ps += __shfl_xor_sync(0xffffffffu, ps, 1);
            ps += __shfl_xor_sync(0xffffffffu, ps, 2);
            if ((lane & 3) == 0) sRed[wn * 64 + r] = ps;
        }
    __syncthreads();
    if (tid < 64)
        frowS[tid] = SCALE / (sRed[tid] + sRed[64 + tid] + sRed[128 + tid] + sRed[192 + tid]);
#pragma unroll
    for (int mi = 0; mi < 2; mi++)
#pragma unroll
        for (int ni = 0; ni < 8; ni++)
#pragma unroll
            for (int j = 0; j < 4; j++) acc[mi][ni][j] = 0.f;
    __syncthreads();

    // ======== phase C: O = P . Vt^T (A = HQ, B streams BS<->TT) =============
    for (int sc = 0; sc < 4; sc++) {
        if (sc < 3) {
            tile_cp(sb + ((sc & 1) ? A_BS : A_TT), Vg + (sc + 1) * 64, 256, tid, 256);
            CP_COMMIT(); CP_WAIT1();
        } else CP_WAIT0();
        __syncthreads();
        uint32_t aB = sb + A_HQ + sc * 8192;
        uint32_t bB = sb + ((sc & 1) ? A_TT : A_BS);
#pragma unroll
        for (int kk = 0; kk < 4; kk++) {
            int ksg = kk * 2;
            uint32_t a[2][4];
#pragma unroll
            for (int mi = 0; mi < 2; mi++)
                ldmat4(a[mi][0], a[mi][1], a[mi][2], a[mi][3], a_addr(aB, wm * 32 + mi * 16, ksg, lane));
#pragma unroll
            for (int nj = 0; nj < 4; nj++) {
                uint32_t r0, r1, r2, r3;
                ldmat4(r0, r1, r2, r3, b_addr(bB, wn * 64 + nj * 16, ksg, lane));
                uint32_t b0[2] = {r0, r1}, b1v[2] = {r2, r3};
#pragma unroll
                for (int mi = 0; mi < 2; mi++) {
                    mma16816(acc[mi][nj * 2],     a[mi], b0);
                    mma16816(acc[mi][nj * 2 + 1], a[mi], b1v);
                }
            }
        }
        __syncthreads();
    }

    // ---- epilogue ----
    float* Os  = (float*)smem_dyn;                 // [64][257]
    float* sp1 = (float*)(smem_dyn + A_SP1);
    float* sp2 = (float*)(smem_dyn + A_SP2);
#pragma unroll
    for (int mi = 0; mi < 2; mi++)
#pragma unroll
        for (int h = 0; h < 2; h++) {
            int r = wm * 32 + mi * 16 + h * 8 + (lane >> 2);
            float fr = frowS[r];
#pragma unroll
            for (int ni = 0; ni < 8; ni++) {
                int d = wn * 64 + ni * 8 + (lane & 3) * 2;
                Os[r * 257 + d]     = acc[mi][ni][h * 2 + 0] * fr;
                Os[r * 257 + d + 1] = acc[mi][ni][h * 2 + 1] * fr;
            }
        }
    __syncthreads();

    int b = bk >> 7, kk2 = bk & 127;
    const float* xb = x   + (size_t)b * (N_ * Kd * S_) + kk2 * S_ + q0;
    float*       ob = out + (size_t)b * (N_ * Kd * S_) + kk2 * S_ + q0;

    {
        int qb4 = (tid & 15) * 4;
        int d0  = tid >> 4;
        float s1[4] = {0.f, 0.f, 0.f, 0.f};
        float s2[4] = {0.f, 0.f, 0.f, 0.f};
#pragma unroll
        for (int it = 0; it < 16; it++) {
            int d = it * 16 + d0;
            float4 xv = *(const float4*)(xb + (size_t)d * (Kd * S_) + qb4);
            float4 pe = *(const float4*)(g_peT + (size_t)d * S_ + q0 + qb4);
            float w1v = w1s[d], b1v = b1s[d];
            float v0 = Os[(qb4 + 0) * 257 + d] + (xv.x - mu1s[qb4 + 0]) * rs1s[qb4 + 0] * w1v + b1v + pe.x;
            float v1 = Os[(qb4 + 1) * 257 + d] + (xv.y - mu1s[qb4 + 1]) * rs1s[qb4 + 1] * w1v + b1v + pe.y;
            float v2 = Os[(qb4 + 2) * 257 + d] + (xv.z - mu1s[qb4 + 2]) * rs1s[qb4 + 2] * w1v + b1v + pe.z;
            float v3 = Os[(qb4 + 3) * 257 + d] + (xv.w - mu1s[qb4 + 3]) * rs1s[qb4 + 3] * w1v + b1v + pe.w;
            Os[(qb4 + 0) * 257 + d] = v0;
            Os[(qb4 + 1) * 257 + d] = v1;
            Os[(qb4 + 2) * 257 + d] = v2;
            Os[(qb4 + 3) * 257 + d] = v3;
            s1[0] += v0; s2[0] += v0 * v0;
            s1[1] += v1; s2[1] += v1 * v1;
            s1[2] += v2; s2[2] += v2 * v2;
            s1[3] += v3; s2[3] += v3 * v3;
        }
#pragma unroll
        for (int i = 0; i < 4; i++) {
            sp1[d0 * 64 + qb4 + i] = s1[i];
            sp2[d0 * 64 + qb4 + i] = s2[i];
        }
    }
    __syncthreads();

    if (tid < 64) {
        float s1 = 0.f, s2 = 0.f;
#pragma unroll
        for (int g = 0; g < 16; g++) { s1 += sp1[g * 64 + tid]; s2 += sp2[g * 64 + tid]; }
        float mu = s1 * (1.f / N_);
        float var = s2 * (1.f / N_) - mu * mu;
        mu2s[tid] = mu;
        rs2s[tid] = rsqrtf(var + 1e-5f);
    }
    __syncthreads();

    {
        int qb4 = (tid & 15) * 4;
        int d0  = tid >> 4;
#pragma unroll
        for (int it = 0; it < 16; it++) {
            int d = it * 16 + d0;
            float4 xv = *(const float4*)(xb + (size_t)d * (Kd * S_) + qb4);
            float w2v = w2s[d], b2v = b2s[d];
            float4 o;
            o.x = (Os[(qb4 + 0) * 257 + d] - mu2s[qb4 + 0]) * rs2s[qb4 + 0] * w2v + b2v + xv.x;
            o.y = (Os[(qb4 + 1) * 257 + d] - mu2s[qb4 + 1]) * rs2s[qb4 + 1] * w2v + b2v + xv.y;
            o.z = (Os[(qb4 + 2) * 257 + d] - mu2s[qb4 + 2]) * rs2s[qb4 + 2] * w2v + b2v + xv.z;
            o.w = (Os[(qb4 + 3) * 257 + d] - mu2s[qb4 + 3]) * rs2s[qb4 + 3] * w2v + b2v + xv.w;
            *(float4*)(ob + (size_t)d * (Kd * S_) + qb4) = o;
        }
    }
}

extern "C" void kernel_launch(void* const* d_in, const int* in_sizes, int n_in,
                              void* d_out, int out_size) {
    const float* x    = (const float*)d_in[0];
    const float* ln1w = (const float*)d_in[1];
    const float* ln1b = (const float*)d_in[2];
    const float* qw   = (const float*)d_in[3];
    const float* qb   = (const float*)d_in[4];
    const float* kw   = (const float*)d_in[5];
    const float* kb   = (const float*)d_in[6];
    const float* vw   = (const float*)d_in[7];
    const float* vb   = (const float*)d_in[8];
    const float* w2   = (const float*)d_in[9];
    const float* b2   = (const float*)d_in[10];
    float* out = (float*)d_out;

    cudaFuncSetAttribute(v_mma,    cudaFuncAttributeMaxDynamicSharedMemorySize, Q_SMEM);
    cudaFuncSetAttribute(attn_mma, cudaFuncAttributeMaxDynamicSharedMemorySize, A_SMEM);

    setup_kernel<<<256, 256>>>(qw, kw, qb, vw);
    ln1_kernel<<<dim3(BKt, 2), 256>>>(x, ln1w, ln1b);
    v_mma<<<dim3(4, BKt), 256, Q_SMEM>>>(vb);
    attn_mma<<<dim3(4, BKt), 256, A_SMEM>>>(x, out, w2, b2, ln1w, ln1b);
}